// round 1
// baseline (speedup 1.0000x reference)
#include <cuda_runtime.h>
#include <math.h>

#define N_TIME   512
#define LATENT   32
#define HIDDEN   64
#define N_MODES  8
#define IN_DIM   (LATENT + 1 + 2 * N_MODES)   // 65
#define X_A0     0.3f
#define CSANMAX  28700.0f
// log(0.3 / 0.7)
#define BASE_LOGIT (-0.8472978603872034f)
#define PI_F 3.14159265358979323846f

#define TPB 256

__global__ __launch_bounds__(TPB, 2)
void slfm_kernel(const int* __restrict__ time_idx,
                 const float* __restrict__ rho,
                 const float* __restrict__ emb,
                 const float* __restrict__ W0,
                 const float* __restrict__ b0,
                 const float* __restrict__ W1,
                 const float* __restrict__ b1,
                 const float* __restrict__ Wout,
                 const float* __restrict__ bout,
                 float* __restrict__ out,
                 int n)
{
    // ---- stage weights into shared memory (broadcast reads later) ----
    __shared__ float sW0[IN_DIM * HIDDEN];   // 65*64 = 4160 floats
    __shared__ float sW1[HIDDEN * HIDDEN];   // 64*64 = 4096 floats
    __shared__ float sB0[HIDDEN];
    __shared__ float sB1[HIDDEN];
    __shared__ float sWo[HIDDEN];
    __shared__ float sBo;

    for (int i = threadIdx.x; i < IN_DIM * HIDDEN; i += TPB) sW0[i] = W0[i];
    for (int i = threadIdx.x; i < HIDDEN * HIDDEN; i += TPB) sW1[i] = W1[i];
    if (threadIdx.x < HIDDEN) {
        sB0[threadIdx.x] = b0[threadIdx.x];
        sB1[threadIdx.x] = b1[threadIdx.x];
        sWo[threadIdx.x] = Wout[threadIdx.x];
    }
    if (threadIdx.x == 0) sBo = bout[0];
    __syncthreads();

    int gid = blockIdx.x * TPB + threadIdx.x;
    if (gid >= n) return;

    int   t = time_idx[gid];
    float r = rho[gid];
    int idx = t - 1;
    idx = idx < 0 ? 0 : (idx > (N_TIME - 2) ? (N_TIME - 2) : idx);

    // ---- layer 0 accumulators ----
    float acc[HIDDEN];
    #pragma unroll
    for (int j = 0; j < HIDDEN; j++) acc[j] = sB0[j];

    // fma one input row into all 64 accumulators (weights broadcast from smem)
    #define FMA_ROW(ROW, XV)                                                   \
    do {                                                                       \
        const float4* _w = reinterpret_cast<const float4*>(sW0 + (ROW) * HIDDEN); \
        float _x = (XV);                                                       \
        _Pragma("unroll")                                                      \
        for (int _j = 0; _j < HIDDEN / 4; _j++) {                              \
            float4 wv = _w[_j];                                                \
            acc[4*_j+0] = fmaf(_x, wv.x, acc[4*_j+0]);                         \
            acc[4*_j+1] = fmaf(_x, wv.y, acc[4*_j+1]);                         \
            acc[4*_j+2] = fmaf(_x, wv.z, acc[4*_j+2]);                         \
            acc[4*_j+3] = fmaf(_x, wv.w, acc[4*_j+3]);                         \
        }                                                                      \
    } while (0)

    // emb rows 0..31 (table is L1/L2 resident; 8x LDG.128)
    const float4* erow = reinterpret_cast<const float4*>(emb + (size_t)idx * LATENT);
    #pragma unroll
    for (int k = 0; k < LATENT / 4; k++) {
        float4 ev = erow[k];
        FMA_ROW(4*k + 0, ev.x);
        FMA_ROW(4*k + 1, ev.y);
        FMA_ROW(4*k + 2, ev.z);
        FMA_ROW(4*k + 3, ev.w);
    }

    // row 32: rho
    FMA_ROW(LATENT, r);

    // rows 33..40: cos(k*pi*r), rows 41..48: sin(k*pi*r) via recurrence
    float s1, c1;
    sincosf(PI_F * r, &s1, &c1);
    float ck = c1, sk = s1;
    FMA_ROW(LATENT + 1, ck);
    FMA_ROW(LATENT + 1 + N_MODES, sk);
    #pragma unroll
    for (int k = 2; k <= N_MODES; k++) {
        float cn = fmaf(ck, c1, -sk * s1);
        float sn = fmaf(sk, c1,  ck * s1);
        ck = cn; sk = sn;
        FMA_ROW(LATENT + k, ck);
        FMA_ROW(LATENT + N_MODES + k, sk);
    }
    #undef FMA_ROW

    // SiLU in place
    #pragma unroll
    for (int j = 0; j < HIDDEN; j++) {
        float v = acc[j];
        acc[j] = v / (1.0f + __expf(-v));
    }

    // ---- layer 1 + output, chunked 4x16 to bound register pressure ----
    float outv = sBo;
    #pragma unroll
    for (int c = 0; c < HIDDEN / 16; c++) {
        float a2[16];
        #pragma unroll
        for (int j = 0; j < 16; j++) a2[j] = sB1[c * 16 + j];

        #pragma unroll 4
        for (int i2 = 0; i2 < HIDDEN; i2++) {
            float h = acc[i2];
            const float4* w = reinterpret_cast<const float4*>(sW1 + i2 * HIDDEN + c * 16);
            #pragma unroll
            for (int q = 0; q < 4; q++) {
                float4 wv = w[q];
                a2[4*q+0] = fmaf(h, wv.x, a2[4*q+0]);
                a2[4*q+1] = fmaf(h, wv.y, a2[4*q+1]);
                a2[4*q+2] = fmaf(h, wv.z, a2[4*q+2]);
                a2[4*q+3] = fmaf(h, wv.w, a2[4*q+3]);
            }
        }
        #pragma unroll
        for (int j = 0; j < 16; j++) {
            float v  = a2[j];
            float sv = v / (1.0f + __expf(-v));
            outv = fmaf(sv, sWo[c * 16 + j], outv);
        }
    }

    float theta = 1.0f / (1.0f + __expf(-(outv + BASE_LOGIT)));
    float res = (t == 0) ? (X_A0 * CSANMAX) : theta * CSANMAX;
    out[gid] = res;
}

extern "C" void kernel_launch(void* const* d_in, const int* in_sizes, int n_in,
                              void* d_out, int out_size)
{
    const int*   time_idx = (const int*)  d_in[0];
    const float* rho      = (const float*)d_in[1];
    const float* emb      = (const float*)d_in[2];
    const float* W0       = (const float*)d_in[3];
    const float* b0       = (const float*)d_in[4];
    const float* W1       = (const float*)d_in[5];
    const float* b1       = (const float*)d_in[6];
    const float* Wout     = (const float*)d_in[7];
    const float* bout     = (const float*)d_in[8];
    float* out = (float*)d_out;

    int n = in_sizes[0];
    int grid = (n + TPB - 1) / TPB;
    slfm_kernel<<<grid, TPB>>>(time_idx, rho, emb, W0, b0, W1, b1,
                               Wout, bout, out, n);
}

// round 2
// speedup vs baseline: 1.7415x; 1.7415x over previous
#include <cuda_runtime.h>
#include <math.h>

#define N_TIME   512
#define LATENT   32
#define HIDDEN   64
#define N_MODES  8
#define IN_DIM   (LATENT + 1 + 2 * N_MODES)   // 65
#define X_A0     0.3f
#define CSANMAX  28700.0f
#define BASE_LOGIT (-0.8472978603872034f)
#define PI_F 3.14159265358979323846f

#define TPB 256

typedef unsigned long long u64;

__device__ __forceinline__ u64 pack2(float x, float y) {
    u64 r; asm("mov.b64 %0, {%1, %2};" : "=l"(r) : "f"(x), "f"(y)); return r;
}
__device__ __forceinline__ u64 dup2(float x) {
    u64 r; asm("mov.b64 %0, {%1, %1};" : "=l"(r) : "f"(x)); return r;
}
__device__ __forceinline__ void unpack2(u64 v, float& x, float& y) {
    asm("mov.b64 {%0, %1}, %2;" : "=f"(x), "=f"(y) : "l"(v));
}
// d = a * b + d  (elementwise on packed f32x2)
__device__ __forceinline__ void ffma2(u64& d, u64 a, u64 b) {
    asm("fma.rn.f32x2 %0, %1, %2, %0;" : "+l"(d) : "l"(a), "l"(b));
}

__device__ __forceinline__ float fast_silu(float v) {
    float den = 1.0f + __expf(-v);
    return __fdividef(v, den);
}

// One input row into all 64 hidden accumulators for BOTH points.
// 16 x LDS.128 (weights, shared) + 64 x FFMA2.
__device__ __forceinline__ void row2(u64* __restrict__ h0, u64* __restrict__ h1,
                                     const float* __restrict__ wrow,
                                     float x0, float x1)
{
    u64 a0 = dup2(x0);
    u64 a1 = dup2(x1);
    const ulonglong2* w = reinterpret_cast<const ulonglong2*>(wrow);
    #pragma unroll
    for (int q = 0; q < 16; q++) {
        ulonglong2 wv = w[q];
        ffma2(h0[2*q],   a0, wv.x);
        ffma2(h0[2*q+1], a0, wv.y);
        ffma2(h1[2*q],   a1, wv.x);
        ffma2(h1[2*q+1], a1, wv.y);
    }
}

__global__ __launch_bounds__(TPB)
void slfm_kernel(const int* __restrict__ time_idx,
                 const float* __restrict__ rho,
                 const float* __restrict__ emb,
                 const float* __restrict__ W0,
                 const float* __restrict__ b0,
                 const float* __restrict__ W1,
                 const float* __restrict__ b1,
                 const float* __restrict__ Wout,
                 const float* __restrict__ bout,
                 float* __restrict__ out,
                 int n, int half)
{
    __shared__ float sW0[IN_DIM * HIDDEN];   // 65*64
    __shared__ float sW1[HIDDEN * HIDDEN];   // 64*64
    __shared__ float sB0[HIDDEN];
    __shared__ float sB1[HIDDEN];
    __shared__ float sWo[HIDDEN];
    __shared__ float sBo;

    for (int i = threadIdx.x; i < IN_DIM * HIDDEN; i += TPB) sW0[i] = W0[i];
    for (int i = threadIdx.x; i < HIDDEN * HIDDEN; i += TPB) sW1[i] = W1[i];
    if (threadIdx.x < HIDDEN) {
        sB0[threadIdx.x] = b0[threadIdx.x];
        sB1[threadIdx.x] = b1[threadIdx.x];
        sWo[threadIdx.x] = Wout[threadIdx.x];
    }
    if (threadIdx.x == 0) sBo = bout[0];
    __syncthreads();

    int gid = blockIdx.x * TPB + threadIdx.x;
    if (gid >= half) return;

    int p0 = gid;
    int p1 = gid + half;
    bool has1 = (p1 < n);
    int p1s = has1 ? p1 : p0;

    int   t0 = time_idx[p0];
    int   t1 = time_idx[p1s];
    float r0 = rho[p0];
    float r1 = rho[p1s];

    int idx0 = t0 - 1; idx0 = idx0 < 0 ? 0 : (idx0 > N_TIME - 2 ? N_TIME - 2 : idx0);
    int idx1 = t1 - 1; idx1 = idx1 < 0 ? 0 : (idx1 > N_TIME - 2 ? N_TIME - 2 : idx1);

    // ---------------- layer 0 ----------------
    // h pairs: h0[j] = {acc[2j], acc[2j+1]} for point 0; h1 likewise for point 1
    u64 h0[HIDDEN / 2], h1[HIDDEN / 2];
    {
        const u64* bb = reinterpret_cast<const u64*>(sB0);
        #pragma unroll
        for (int j = 0; j < HIDDEN / 2; j++) { u64 b = bb[j]; h0[j] = b; h1[j] = b; }
    }

    // emb rows 0..31
    const float4* e0 = reinterpret_cast<const float4*>(emb + (size_t)idx0 * LATENT);
    const float4* e1 = reinterpret_cast<const float4*>(emb + (size_t)idx1 * LATENT);
    #pragma unroll 2
    for (int k = 0; k < LATENT / 4; k++) {
        float4 v0 = e0[k];
        float4 v1 = e1[k];
        const float* w = sW0 + (4 * k) * HIDDEN;
        row2(h0, h1, w,               v0.x, v1.x);
        row2(h0, h1, w + HIDDEN,      v0.y, v1.y);
        row2(h0, h1, w + 2 * HIDDEN,  v0.z, v1.z);
        row2(h0, h1, w + 3 * HIDDEN,  v0.w, v1.w);
    }

    // row 32: rho
    row2(h0, h1, sW0 + LATENT * HIDDEN, r0, r1);

    // rows 33..40 cos, 41..48 sin via angle-addition recurrence
    float s10, c10, s11, c11;
    sincosf(PI_F * r0, &s10, &c10);
    sincosf(PI_F * r1, &s11, &c11);
    float ck0 = c10, sk0 = s10, ck1 = c11, sk1 = s11;
    row2(h0, h1, sW0 + (LATENT + 1) * HIDDEN,            ck0, ck1);
    row2(h0, h1, sW0 + (LATENT + 1 + N_MODES) * HIDDEN,  sk0, sk1);
    #pragma unroll 1
    for (int k = 2; k <= N_MODES; k++) {
        float cn0 = fmaf(ck0, c10, -sk0 * s10);
        float sn0 = fmaf(sk0, c10,  ck0 * s10);
        float cn1 = fmaf(ck1, c11, -sk1 * s11);
        float sn1 = fmaf(sk1, c11,  ck1 * s11);
        ck0 = cn0; sk0 = sn0; ck1 = cn1; sk1 = sn1;
        row2(h0, h1, sW0 + (LATENT + k) * HIDDEN,           ck0, ck1);
        row2(h0, h1, sW0 + (LATENT + N_MODES + k) * HIDDEN, sk0, sk1);
    }

    // SiLU -> scalar h arrays (for per-k dup in layer 1)
    float hs0[HIDDEN], hs1[HIDDEN];
    #pragma unroll
    for (int j = 0; j < HIDDEN / 2; j++) {
        float a, b;
        unpack2(h0[j], a, b);
        hs0[2*j]   = fast_silu(a);
        hs0[2*j+1] = fast_silu(b);
        unpack2(h1[j], a, b);
        hs1[2*j]   = fast_silu(a);
        hs1[2*j+1] = fast_silu(b);
    }

    // ---------------- layer 1 + output, 4 chunks of 16 hidden ----------------
    float outv0 = sBo;
    float outv1 = sBo;
    #pragma unroll 1
    for (int c = 0; c < 4; c++) {
        u64 a20[8], a21[8];
        const u64* bb1 = reinterpret_cast<const u64*>(sB1);
        #pragma unroll
        for (int q = 0; q < 8; q++) { u64 b = bb1[c * 8 + q]; a20[q] = b; a21[q] = b; }

        const float* wbase = sW1 + c * 16;
        #pragma unroll
        for (int k = 0; k < HIDDEN; k++) {
            u64 a0 = dup2(hs0[k]);
            u64 a1 = dup2(hs1[k]);
            const ulonglong2* w = reinterpret_cast<const ulonglong2*>(wbase + k * HIDDEN);
            ulonglong2 w0 = w[0];
            ulonglong2 w1 = w[1];
            ffma2(a20[0], a0, w0.x); ffma2(a20[1], a0, w0.y);
            ffma2(a20[2], a0, w1.x); ffma2(a20[3], a0, w1.y);
            ffma2(a21[0], a1, w0.x); ffma2(a21[1], a1, w0.y);
            ffma2(a21[2], a1, w1.x); ffma2(a21[3], a1, w1.y);
            const ulonglong2* w2 = w + 2;
            ulonglong2 w4 = w2[0];
            ulonglong2 w5 = w2[1];
            ffma2(a20[4], a0, w4.x); ffma2(a20[5], a0, w4.y);
            ffma2(a20[6], a0, w5.x); ffma2(a20[7], a0, w5.y);
            ffma2(a21[4], a1, w4.x); ffma2(a21[5], a1, w4.y);
            ffma2(a21[6], a1, w5.x); ffma2(a21[7], a1, w5.y);
        }

        #pragma unroll
        for (int q = 0; q < 8; q++) {
            float a, b;
            int j = c * 16 + 2 * q;
            float woa = sWo[j], wob = sWo[j + 1];
            unpack2(a20[q], a, b);
            outv0 = fmaf(fast_silu(a), woa, outv0);
            outv0 = fmaf(fast_silu(b), wob, outv0);
            unpack2(a21[q], a, b);
            outv1 = fmaf(fast_silu(a), woa, outv1);
            outv1 = fmaf(fast_silu(b), wob, outv1);
        }
    }

    float th0 = __fdividef(1.0f, 1.0f + __expf(-(outv0 + BASE_LOGIT)));
    float th1 = __fdividef(1.0f, 1.0f + __expf(-(outv1 + BASE_LOGIT)));
    float res0 = (t0 == 0) ? (X_A0 * CSANMAX) : th0 * CSANMAX;
    float res1 = (t1 == 0) ? (X_A0 * CSANMAX) : th1 * CSANMAX;

    out[p0] = res0;
    if (has1) out[p1] = res1;
}

extern "C" void kernel_launch(void* const* d_in, const int* in_sizes, int n_in,
                              void* d_out, int out_size)
{
    const int*   time_idx = (const int*)  d_in[0];
    const float* rho      = (const float*)d_in[1];
    const float* emb      = (const float*)d_in[2];
    const float* W0       = (const float*)d_in[3];
    const float* b0       = (const float*)d_in[4];
    const float* W1       = (const float*)d_in[5];
    const float* b1       = (const float*)d_in[6];
    const float* Wout     = (const float*)d_in[7];
    const float* bout     = (const float*)d_in[8];
    float* out = (float*)d_out;

    int n = in_sizes[0];
    int half = (n + 1) / 2;
    int grid = (half + TPB - 1) / TPB;
    slfm_kernel<<<grid, TPB>>>(time_idx, rho, emb, W0, b0, W1, b1,
                               Wout, bout, out, n, half);
}

// round 5
// speedup vs baseline: 3.2935x; 1.8912x over previous
#include <cuda_runtime.h>
#include <cuda_bf16.h>
#include <cstdint>
#include <math.h>

#define N_TIME   512
#define LATENT   32
#define HIDDEN   64
#define N_MODES  8
#define IN_DIM   49
#define X_A0     0.3f
#define CSANMAX  28700.0f
#define BASE_LOGIT (-0.8472978603872034f)
#define PI_F 3.14159265358979323846f

#define TPB       128
#define M_TILE    128
#define GRID_CTAS 296

#define ROW_STRIDE 72   // bf16 elems per feature row (144 B -> bank = 4g + t4, conflict-free)

// ---- smem layout (bytes) ----
#define SM_AHI 0
#define SM_ALO (SM_AHI + M_TILE * ROW_STRIDE * 2)   // 18432
#define SM_F0H (SM_ALO + M_TILE * ROW_STRIDE * 2)   // 36864
#define SM_F0L (SM_F0H + 8192)
#define SM_F1H (SM_F0L + 8192)
#define SM_F1L (SM_F1H + 8192)
#define SM_B0  (SM_F1L + 8192)                      // 69632
#define SM_B1  (SM_B0 + 256)
#define SM_WO  (SM_B1 + 256)
#define SM_BO  (SM_WO + 256)
#define SM_TOTAL (SM_BO + 16)

typedef uint32_t u32;
typedef uint64_t u64;

// pack two fp32 -> bf16x2, first arg in LOW half
__device__ __forceinline__ u32 pk(float lo, float hi) {
    u32 r;
    asm("cvt.rn.bf16x2.f32 %0, %1, %2;" : "=r"(r) : "f"(hi), "f"(lo));
    return r;
}
__device__ __forceinline__ float bf_lo(u32 p) { return __uint_as_float(p << 16); }
__device__ __forceinline__ float bf_hi(u32 p) { return __uint_as_float(p & 0xffff0000u); }

__device__ __forceinline__ float fast_silu(float v) {
    return __fdividef(v, 1.0f + __expf(-v));
}

__device__ __forceinline__ void mma_bf16(float* d, u32 a0, u32 a1, u32 a2, u32 a3,
                                         u32 b0, u32 b1) {
    asm volatile("mma.sync.aligned.m16n8k16.row.col.f32.bf16.bf16.f32 "
                 "{%0,%1,%2,%3}, {%4,%5,%6,%7}, {%8,%9}, {%0,%1,%2,%3};"
                 : "+f"(d[0]), "+f"(d[1]), "+f"(d[2]), "+f"(d[3])
                 : "r"(a0), "r"(a1), "r"(a2), "r"(a3), "r"(b0), "r"(b1));
}

// split 8 consecutive fp32 -> hi/lo bf16x2 quads
__device__ __forceinline__ void split8(const float* x, uint4& hv, uint4& lv) {
    u32 h[4], l[4];
    #pragma unroll
    for (int q = 0; q < 4; q++) {
        float a = x[2*q], b = x[2*q+1];
        u32 p = pk(a, b);
        h[q] = p;
        l[q] = pk(a - bf_lo(p), b - bf_hi(p));
    }
    hv = make_uint4(h[0], h[1], h[2], h[3]);
    lv = make_uint4(l[0], l[1], l[2], l[3]);
}

// one GEMM layer: A (smem hi/lo, rows rowA..rowA+31) x B (frag arrays) -> d[2][8][4]
// A-fragment row for reg0 is rowA + mt*16 + g  (g = lane>>2)  [FIXED]
__device__ __forceinline__ void gemm_layer(char* smem, int fHiOff, int fLoOff,
                                           int rowA, int lane, int g, int t4,
                                           float d[2][8][4]) {
    #pragma unroll
    for (int ks = 0; ks < 4; ks++) {
        int k0 = ks * 16 + t4 * 2;
        u32 ah[2][4], al[2][4];
        #pragma unroll
        for (int mt = 0; mt < 2; mt++) {
            int r = rowA + mt * 16 + g;   // <-- includes groupID now
            int base = (r * ROW_STRIDE + k0) * 2;
            ah[mt][0] = *(const u32*)(smem + SM_AHI + base);
            ah[mt][1] = *(const u32*)(smem + SM_AHI + base + 8 * ROW_STRIDE * 2);
            ah[mt][2] = *(const u32*)(smem + SM_AHI + base + 16);
            ah[mt][3] = *(const u32*)(smem + SM_AHI + base + 8 * ROW_STRIDE * 2 + 16);
            al[mt][0] = *(const u32*)(smem + SM_ALO + base);
            al[mt][1] = *(const u32*)(smem + SM_ALO + base + 8 * ROW_STRIDE * 2);
            al[mt][2] = *(const u32*)(smem + SM_ALO + base + 16);
            al[mt][3] = *(const u32*)(smem + SM_ALO + base + 8 * ROW_STRIDE * 2 + 16);
        }
        #pragma unroll
        for (int nt = 0; nt < 8; nt++) {
            int foff = ((ks * 8 + nt) * 32 + lane) * 8;
            u64 bh = *(const u64*)(smem + fHiOff + foff);
            u64 bl = *(const u64*)(smem + fLoOff + foff);
            u32 bh0 = (u32)bh, bh1 = (u32)(bh >> 32);
            u32 bl0 = (u32)bl, bl1 = (u32)(bl >> 32);
            #pragma unroll
            for (int mt = 0; mt < 2; mt++) {
                mma_bf16(d[mt][nt], ah[mt][0], ah[mt][1], ah[mt][2], ah[mt][3], bh0, bh1);
                mma_bf16(d[mt][nt], ah[mt][0], ah[mt][1], ah[mt][2], ah[mt][3], bl0, bl1);
                mma_bf16(d[mt][nt], al[mt][0], al[mt][1], al[mt][2], al[mt][3], bh0, bh1);
            }
        }
    }
}

__global__ __launch_bounds__(TPB, 2)
void slfm_hmma_kernel(const int* __restrict__ time_idx,
                      const float* __restrict__ rho,
                      const float* __restrict__ emb,
                      const float* __restrict__ W0,
                      const float* __restrict__ b0g,
                      const float* __restrict__ W1,
                      const float* __restrict__ b1g,
                      const float* __restrict__ Woutg,
                      const float* __restrict__ boutg,
                      float* __restrict__ outp,
                      int n, int ntiles)
{
    extern __shared__ char smem[];
    const int tid  = threadIdx.x;
    const int lane = tid & 31;
    const int warp = tid >> 5;
    const int g    = lane >> 2;
    const int t4   = lane & 3;
    const int rowA = warp * 32;

    // ---- stage weight fragments (m16n8k16 B fragment layout) ----
    // slot (ks, nt, lane): reg0 = {W[k0][n], W[k0+1][n]}, reg1 = {W[k0+8][n], W[k0+9][n]}
    // with n = nt*8 + (lane>>2), k0 = ks*16 + (lane&3)*2
    for (int i = tid; i < 1024; i += TPB) {
        int ks = i >> 8, nt = (i >> 5) & 7, ln = i & 31;
        int gg = ln >> 2, tt = ln & 3;
        int nn = nt * 8 + gg;
        int k0 = ks * 16 + tt * 2;

        float w00 = (k0     < IN_DIM) ? W0[(k0    ) * HIDDEN + nn] : 0.0f;
        float w01 = (k0 + 1 < IN_DIM) ? W0[(k0 + 1) * HIDDEN + nn] : 0.0f;
        float w08 = (k0 + 8 < IN_DIM) ? W0[(k0 + 8) * HIDDEN + nn] : 0.0f;
        float w09 = (k0 + 9 < IN_DIM) ? W0[(k0 + 9) * HIDDEN + nn] : 0.0f;
        u32 h0 = pk(w00, w01);
        u32 h1 = pk(w08, w09);
        u32 l0 = pk(w00 - bf_lo(h0), w01 - bf_hi(h0));
        u32 l1 = pk(w08 - bf_lo(h1), w09 - bf_hi(h1));
        int off = ((ks * 8 + nt) * 32 + ln) * 8;
        *(u64*)(smem + SM_F0H + off) = (u64)h0 | ((u64)h1 << 32);
        *(u64*)(smem + SM_F0L + off) = (u64)l0 | ((u64)l1 << 32);

        float v00 = W1[(k0    ) * HIDDEN + nn];
        float v01 = W1[(k0 + 1) * HIDDEN + nn];
        float v08 = W1[(k0 + 8) * HIDDEN + nn];
        float v09 = W1[(k0 + 9) * HIDDEN + nn];
        u32 p0 = pk(v00, v01);
        u32 p1 = pk(v08, v09);
        u32 q0 = pk(v00 - bf_lo(p0), v01 - bf_hi(p0));
        u32 q1 = pk(v08 - bf_lo(p1), v09 - bf_hi(p1));
        *(u64*)(smem + SM_F1H + off) = (u64)p0 | ((u64)p1 << 32);
        *(u64*)(smem + SM_F1L + off) = (u64)q0 | ((u64)q1 << 32);
    }
    if (tid < HIDDEN) {
        ((float*)(smem + SM_B0))[tid] = b0g[tid];
        ((float*)(smem + SM_B1))[tid] = b1g[tid];
        ((float*)(smem + SM_WO))[tid] = Woutg[tid];
    }
    if (tid == 0) *((float*)(smem + SM_BO)) = boutg[0] + BASE_LOGIT;
    __syncthreads();

    // ---- prefetch first tile ----
    int tile = blockIdx.x;
    int   t_c = 0;
    float r_c = 0.0f;
    float4 e_c[8];
    if (tile < ntiles) {
        int p = tile * M_TILE + tid;
        int ps = p < n ? p : n - 1;
        t_c = time_idx[ps];
        r_c = rho[ps];
        int idx = t_c - 1;
        idx = idx < 0 ? 0 : (idx > N_TIME - 2 ? N_TIME - 2 : idx);
        const float4* er = (const float4*)(emb + (size_t)idx * LATENT);
        #pragma unroll
        for (int q = 0; q < 8; q++) e_c[q] = er[q];
    }

    for (; tile < ntiles; tile += GRID_CTAS) {
        // ---------- build features for own point (row = tid), split, store ----------
        {
            float xv[64];
            #pragma unroll
            for (int q = 0; q < 8; q++) {
                xv[4*q+0] = e_c[q].x; xv[4*q+1] = e_c[q].y;
                xv[4*q+2] = e_c[q].z; xv[4*q+3] = e_c[q].w;
            }
            xv[32] = r_c;
            float s1, c1;
            sincosf(PI_F * r_c, &s1, &c1);
            float ck = c1, sk = s1;
            xv[33] = ck; xv[41] = sk;
            #pragma unroll
            for (int k = 2; k <= N_MODES; k++) {
                float cn = fmaf(ck, c1, -sk * s1);
                float sn = fmaf(sk, c1,  ck * s1);
                ck = cn; sk = sn;
                xv[32 + k] = ck;
                xv[40 + k] = sk;
            }
            #pragma unroll
            for (int k = 49; k < 64; k++) xv[k] = 0.0f;

            #pragma unroll
            for (int gq = 0; gq < 8; gq++) {
                uint4 hv, lv;
                split8(xv + 8 * gq, hv, lv);
                int off = (tid * ROW_STRIDE + gq * 8) * 2;
                *(uint4*)(smem + SM_AHI + off) = hv;
                *(uint4*)(smem + SM_ALO + off) = lv;
            }
        }
        __syncwarp();

        // ---------- prefetch next tile (overlaps compute) ----------
        int ntile2 = tile + GRID_CTAS;
        int   t_n = 0;
        float r_n = 0.0f;
        float4 e_n[8];
        if (ntile2 < ntiles) {
            int p = ntile2 * M_TILE + tid;
            int ps = p < n ? p : n - 1;
            t_n = time_idx[ps];
            r_n = rho[ps];
            int idx = t_n - 1;
            idx = idx < 0 ? 0 : (idx > N_TIME - 2 ? N_TIME - 2 : idx);
            const float4* er = (const float4*)(emb + (size_t)idx * LATENT);
            #pragma unroll
            for (int q = 0; q < 8; q++) e_n[q] = er[q];
        }

        // ---------- layer 0 ----------
        float d0[2][8][4];
        #pragma unroll
        for (int mt = 0; mt < 2; mt++)
            #pragma unroll
            for (int nt = 0; nt < 8; nt++)
                #pragma unroll
                for (int q = 0; q < 4; q++) d0[mt][nt][q] = 0.0f;
        gemm_layer(smem, SM_F0H, SM_F0L, rowA, lane, g, t4, d0);

        // ---------- epilogue 0: +bias, SiLU, split, write H over A ----------
        #pragma unroll
        for (int mt = 0; mt < 2; mt++) {
            int rT = rowA + mt * 16 + g;
            #pragma unroll
            for (int nt = 0; nt < 8; nt++) {
                int n0 = nt * 8 + t4 * 2;
                float2 bb = *(const float2*)(smem + SM_B0 + n0 * 4);
                float v0 = fast_silu(d0[mt][nt][0] + bb.x);
                float v1 = fast_silu(d0[mt][nt][1] + bb.y);
                float v2 = fast_silu(d0[mt][nt][2] + bb.x);
                float v3 = fast_silu(d0[mt][nt][3] + bb.y);
                u32 hT = pk(v0, v1);
                u32 lT = pk(v0 - bf_lo(hT), v1 - bf_hi(hT));
                u32 hB = pk(v2, v3);
                u32 lB = pk(v2 - bf_lo(hB), v3 - bf_hi(hB));
                int offT = (rT * ROW_STRIDE + n0) * 2;
                int offB = ((rT + 8) * ROW_STRIDE + n0) * 2;
                *(u32*)(smem + SM_AHI + offT) = hT;
                *(u32*)(smem + SM_ALO + offT) = lT;
                *(u32*)(smem + SM_AHI + offB) = hB;
                *(u32*)(smem + SM_ALO + offB) = lB;
            }
        }
        __syncwarp();

        // ---------- layer 1 ----------
        float d1[2][8][4];
        #pragma unroll
        for (int mt = 0; mt < 2; mt++)
            #pragma unroll
            for (int nt = 0; nt < 8; nt++)
                #pragma unroll
                for (int q = 0; q < 4; q++) d1[mt][nt][q] = 0.0f;
        gemm_layer(smem, SM_F1H, SM_F1L, rowA, lane, g, t4, d1);

        // ---------- final: +b1, SiLU, dot Wout, reduce, sigmoid, store ----------
        {
            float outb = *((const float*)(smem + SM_BO));  // bout + BASE_LOGIT
            #pragma unroll
            for (int mt = 0; mt < 2; mt++) {
                float sT = 0.0f, sB = 0.0f;
                #pragma unroll
                for (int nt = 0; nt < 8; nt++) {
                    int n0 = nt * 8 + t4 * 2;
                    float2 bb = *(const float2*)(smem + SM_B1 + n0 * 4);
                    float2 ww = *(const float2*)(smem + SM_WO + n0 * 4);
                    sT = fmaf(fast_silu(d1[mt][nt][0] + bb.x), ww.x, sT);
                    sT = fmaf(fast_silu(d1[mt][nt][1] + bb.y), ww.y, sT);
                    sB = fmaf(fast_silu(d1[mt][nt][2] + bb.x), ww.x, sB);
                    sB = fmaf(fast_silu(d1[mt][nt][3] + bb.y), ww.y, sB);
                }
                sT += __shfl_xor_sync(0xffffffffu, sT, 1);
                sT += __shfl_xor_sync(0xffffffffu, sT, 2);
                sB += __shfl_xor_sync(0xffffffffu, sB, 1);
                sB += __shfl_xor_sync(0xffffffffu, sB, 2);

                int rlT = mt * 16 + g;       // local row within warp
                int rlB = rlT + 8;
                int tT = __shfl_sync(0xffffffffu, t_c, rlT);
                int tB = __shfl_sync(0xffffffffu, t_c, rlB);

                if (t4 == 0) {
                    int pT = tile * M_TILE + rowA + rlT;
                    int pB = tile * M_TILE + rowA + rlB;
                    float thT = __fdividef(1.0f, 1.0f + __expf(-(sT + outb)));
                    float thB = __fdividef(1.0f, 1.0f + __expf(-(sB + outb)));
                    float oT = (tT == 0) ? (X_A0 * CSANMAX) : thT * CSANMAX;
                    float oB = (tB == 0) ? (X_A0 * CSANMAX) : thB * CSANMAX;
                    if (pT < n) outp[pT] = oT;
                    if (pB < n) outp[pB] = oB;
                }
            }
        }
        __syncwarp();

        // rotate prefetch
        t_c = t_n; r_c = r_n;
        #pragma unroll
        for (int q = 0; q < 8; q++) e_c[q] = e_n[q];
    }
}

extern "C" void kernel_launch(void* const* d_in, const int* in_sizes, int n_in,
                              void* d_out, int out_size)
{
    const int*   time_idx = (const int*)  d_in[0];
    const float* rho      = (const float*)d_in[1];
    const float* emb      = (const float*)d_in[2];
    const float* W0       = (const float*)d_in[3];
    const float* b0       = (const float*)d_in[4];
    const float* W1       = (const float*)d_in[5];
    const float* b1       = (const float*)d_in[6];
    const float* Wout     = (const float*)d_in[7];
    const float* bout     = (const float*)d_in[8];
    float* out = (float*)d_out;

    int n = in_sizes[0];
    int ntiles = (n + M_TILE - 1) / M_TILE;

    cudaFuncSetAttribute(slfm_hmma_kernel,
                         cudaFuncAttributeMaxDynamicSharedMemorySize, SM_TOTAL);
    int grid = ntiles < GRID_CTAS ? ntiles : GRID_CTAS;
    slfm_hmma_kernel<<<grid, TPB, SM_TOTAL>>>(time_idx, rho, emb, W0, b0, W1, b1,
                                              Wout, bout, out, n, ntiles);
}

// round 6
// speedup vs baseline: 4.1228x; 1.2518x over previous
#include <cuda_runtime.h>
#include <cuda_bf16.h>
#include <cstdint>
#include <math.h>

#define N_TIME   512
#define LATENT   32
#define HIDDEN   64
#define N_MODES  8
#define IN_DIM   49
#define X_A0     0.3f
#define CSANMAX  28700.0f
#define BASE_LOGIT (-0.8472978603872034f)
#define PI_F 3.14159265358979323846f

#define TPB       128
#define M_TILE    128
#define GRID_CTAS 296

#define ROW_STRIDE 72   // bf16 elems per feature row (144 B)

// ---- smem layout (bytes) ----
#define SM_AHI 0
#define SM_ALO (SM_AHI + M_TILE * ROW_STRIDE * 2)   // 18432
#define SM_F0H (SM_ALO + M_TILE * ROW_STRIDE * 2)   // 36864
#define SM_F0L (SM_F0H + 8192)
#define SM_F1H (SM_F0L + 8192)
#define SM_F1L (SM_F1H + 8192)
#define SM_B0  (SM_F1L + 8192)                      // 69632
#define SM_B1  (SM_B0 + 256)
#define SM_WO  (SM_B1 + 256)
#define SM_BO  (SM_WO + 256)
#define SM_TOTAL (SM_BO + 16)

typedef uint32_t u32;
typedef uint64_t u64;

__device__ __forceinline__ u32 smem_u32(const void* p) {
    u32 a;
    asm("{ .reg .u64 t; cvta.to.shared.u64 t, %1; cvt.u32.u64 %0, t; }"
        : "=r"(a) : "l"(p));
    return a;
}

// pack two fp32 -> bf16x2, first arg in LOW half
__device__ __forceinline__ u32 pk(float lo, float hi) {
    u32 r;
    asm("cvt.rn.bf16x2.f32 %0, %1, %2;" : "=r"(r) : "f"(hi), "f"(lo));
    return r;
}
__device__ __forceinline__ float bf_lo(u32 p) { return __uint_as_float(p << 16); }
__device__ __forceinline__ float bf_hi(u32 p) { return __uint_as_float(p & 0xffff0000u); }

__device__ __forceinline__ float fast_silu(float v) {
    return __fdividef(v, 1.0f + __expf(-v));
}

__device__ __forceinline__ void mma_bf16(float* d, u32 a0, u32 a1, u32 a2, u32 a3,
                                         u32 b0, u32 b1) {
    asm volatile("mma.sync.aligned.m16n8k16.row.col.f32.bf16.bf16.f32 "
                 "{%0,%1,%2,%3}, {%4,%5,%6,%7}, {%8,%9}, {%0,%1,%2,%3};"
                 : "+f"(d[0]), "+f"(d[1]), "+f"(d[2]), "+f"(d[3])
                 : "r"(a0), "r"(a1), "r"(a2), "r"(a3), "r"(b0), "r"(b1));
}

__device__ __forceinline__ void ldsm_x4(u32& r0, u32& r1, u32& r2, u32& r3, u32 addr) {
    asm volatile("ldmatrix.sync.aligned.m8n8.x4.shared.b16 {%0,%1,%2,%3}, [%4];"
                 : "=r"(r0), "=r"(r1), "=r"(r2), "=r"(r3) : "r"(addr));
}

// split 8 consecutive fp32 -> hi/lo bf16x2 quads
__device__ __forceinline__ void split8(const float* x, uint4& hv, uint4& lv) {
    u32 h[4], l[4];
    #pragma unroll
    for (int q = 0; q < 4; q++) {
        float a = x[2*q], b = x[2*q+1];
        u32 p = pk(a, b);
        h[q] = p;
        l[q] = pk(a - bf_lo(p), b - bf_hi(p));
    }
    hv = make_uint4(h[0], h[1], h[2], h[3]);
    lv = make_uint4(l[0], l[1], l[2], l[3]);
}

__global__ __launch_bounds__(TPB, 2)
void slfm_hmma_kernel(const int* __restrict__ time_idx,
                      const float* __restrict__ rho,
                      const float* __restrict__ emb,
                      const float* __restrict__ W0,
                      const float* __restrict__ b0g,
                      const float* __restrict__ W1,
                      const float* __restrict__ b1g,
                      const float* __restrict__ Woutg,
                      const float* __restrict__ boutg,
                      float* __restrict__ outp,
                      int n, int ntiles)
{
    extern __shared__ char smem[];
    const u32 sb = smem_u32(smem);
    const int tid  = threadIdx.x;
    const int lane = tid & 31;
    const int warp = tid >> 5;
    const int g    = lane >> 2;
    const int t4   = lane & 3;
    const int rowA = warp * 32;

    // ---- stage weight fragments, pair-packed: slot (ks, ntp, lane) is a uint4
    // holding {h0,h1} for nt=2ntp and nt=2ntp+1.
    // B-frag mapping: n = nt*8 + (lane>>2), k0 = ks*16 + (lane&3)*2;
    // reg0 = {W[k0][n],W[k0+1][n]}, reg1 = {W[k0+8][n],W[k0+9][n]}
    for (int i = tid; i < 512; i += TPB) {
        int ks = i >> 7, ntp = (i >> 5) & 3, ln = i & 31;
        int gg = ln >> 2, tt = ln & 3;
        int k0 = ks * 16 + tt * 2;
        u32 a0h[4], a0l[4], a1h[4], a1l[4];
        #pragma unroll
        for (int sub = 0; sub < 2; sub++) {
            int nn = (ntp * 2 + sub) * 8 + gg;
            float w00 = (k0     < IN_DIM) ? W0[(k0    ) * HIDDEN + nn] : 0.0f;
            float w01 = (k0 + 1 < IN_DIM) ? W0[(k0 + 1) * HIDDEN + nn] : 0.0f;
            float w08 = (k0 + 8 < IN_DIM) ? W0[(k0 + 8) * HIDDEN + nn] : 0.0f;
            float w09 = (k0 + 9 < IN_DIM) ? W0[(k0 + 9) * HIDDEN + nn] : 0.0f;
            u32 h0 = pk(w00, w01);
            u32 h1 = pk(w08, w09);
            a0h[sub*2+0] = h0;
            a0h[sub*2+1] = h1;
            a0l[sub*2+0] = pk(w00 - bf_lo(h0), w01 - bf_hi(h0));
            a0l[sub*2+1] = pk(w08 - bf_lo(h1), w09 - bf_hi(h1));

            float v00 = W1[(k0    ) * HIDDEN + nn];
            float v01 = W1[(k0 + 1) * HIDDEN + nn];
            float v08 = W1[(k0 + 8) * HIDDEN + nn];
            float v09 = W1[(k0 + 9) * HIDDEN + nn];
            u32 p0 = pk(v00, v01);
            u32 p1 = pk(v08, v09);
            a1h[sub*2+0] = p0;
            a1h[sub*2+1] = p1;
            a1l[sub*2+0] = pk(v00 - bf_lo(p0), v01 - bf_hi(p0));
            a1l[sub*2+1] = pk(v08 - bf_lo(p1), v09 - bf_hi(p1));
        }
        int off = ((ks * 4 + ntp) * 32 + ln) * 16;
        *(uint4*)(smem + SM_F0H + off) = make_uint4(a0h[0], a0h[1], a0h[2], a0h[3]);
        *(uint4*)(smem + SM_F0L + off) = make_uint4(a0l[0], a0l[1], a0l[2], a0l[3]);
        *(uint4*)(smem + SM_F1H + off) = make_uint4(a1h[0], a1h[1], a1h[2], a1h[3]);
        *(uint4*)(smem + SM_F1L + off) = make_uint4(a1l[0], a1l[1], a1l[2], a1l[3]);
    }
    if (tid < HIDDEN) {
        ((float*)(smem + SM_B0))[tid] = b0g[tid];
        ((float*)(smem + SM_B1))[tid] = b1g[tid];
        ((float*)(smem + SM_WO))[tid] = Woutg[tid];
    }
    if (tid == 0) *((float*)(smem + SM_BO)) = boutg[0] + BASE_LOGIT;
    __syncthreads();

    // ldmatrix per-lane base addresses for feature A (hi / lo)
    const u32 aBaseHi = sb + SM_AHI +
        (u32)(((rowA + (lane & 15)) * ROW_STRIDE + (lane >> 4) * 8) * 2);
    const u32 aBaseLo = aBaseHi + (SM_ALO - SM_AHI);

    // ---- prefetch first tile ----
    int tile = blockIdx.x;
    int   t_c = 0;
    float r_c = 0.0f;
    float4 e_c[8];
    if (tile < ntiles) {
        int p = tile * M_TILE + tid;
        int ps = p < n ? p : n - 1;
        t_c = time_idx[ps];
        r_c = rho[ps];
        int idx = t_c - 1;
        idx = idx < 0 ? 0 : (idx > N_TIME - 2 ? N_TIME - 2 : idx);
        const float4* er = (const float4*)(emb + (size_t)idx * LATENT);
        #pragma unroll
        for (int q = 0; q < 8; q++) e_c[q] = er[q];
    }

    for (; tile < ntiles; tile += GRID_CTAS) {
        // ---------- build features (row = tid), split hi/lo, store ----------
        {
            float xv[64];
            #pragma unroll
            for (int q = 0; q < 8; q++) {
                xv[4*q+0] = e_c[q].x; xv[4*q+1] = e_c[q].y;
                xv[4*q+2] = e_c[q].z; xv[4*q+3] = e_c[q].w;
            }
            xv[32] = r_c;
            float s1, c1;
            sincosf(PI_F * r_c, &s1, &c1);
            float ck = c1, sk = s1;
            xv[33] = ck; xv[41] = sk;
            #pragma unroll
            for (int k = 2; k <= N_MODES; k++) {
                float cn = fmaf(ck, c1, -sk * s1);
                float sn = fmaf(sk, c1,  ck * s1);
                ck = cn; sk = sn;
                xv[32 + k] = ck;
                xv[40 + k] = sk;
            }
            #pragma unroll
            for (int k = 49; k < 64; k++) xv[k] = 0.0f;

            #pragma unroll
            for (int gq = 0; gq < 8; gq++) {
                uint4 hv, lv;
                split8(xv + 8 * gq, hv, lv);
                int off = (tid * ROW_STRIDE + gq * 8) * 2;
                *(uint4*)(smem + SM_AHI + off) = hv;
                *(uint4*)(smem + SM_ALO + off) = lv;
            }
        }
        __syncwarp();

        // ---------- prefetch next tile (overlaps compute) ----------
        int ntile2 = tile + GRID_CTAS;
        int   t_n = 0;
        float r_n = 0.0f;
        float4 e_n[8];
        if (ntile2 < ntiles) {
            int p = ntile2 * M_TILE + tid;
            int ps = p < n ? p : n - 1;
            t_n = time_idx[ps];
            r_n = rho[ps];
            int idx = t_n - 1;
            idx = idx < 0 ? 0 : (idx > N_TIME - 2 ? N_TIME - 2 : idx);
            const float4* er = (const float4*)(emb + (size_t)idx * LATENT);
            #pragma unroll
            for (int q = 0; q < 8; q++) e_n[q] = er[q];
        }

        // ---------- layer 0: A via ldmatrix, B via paired LDS.128 ----------
        float d0[2][8][4];
        #pragma unroll
        for (int mt = 0; mt < 2; mt++)
            #pragma unroll
            for (int nt = 0; nt < 8; nt++)
                #pragma unroll
                for (int q = 0; q < 4; q++) d0[mt][nt][q] = 0.0f;

        #pragma unroll
        for (int ks = 0; ks < 4; ks++) {
            u32 ah[2][4], al[2][4];
            #pragma unroll
            for (int mt = 0; mt < 2; mt++) {
                u32 moff = (u32)(mt * 16 * ROW_STRIDE * 2 + ks * 32);
                ldsm_x4(ah[mt][0], ah[mt][1], ah[mt][2], ah[mt][3], aBaseHi + moff);
                ldsm_x4(al[mt][0], al[mt][1], al[mt][2], al[mt][3], aBaseLo + moff);
            }
            #pragma unroll
            for (int ntp = 0; ntp < 4; ntp++) {
                int off = ((ks * 4 + ntp) * 32 + lane) * 16;
                uint4 bh = *(const uint4*)(smem + SM_F0H + off);
                uint4 bl = *(const uint4*)(smem + SM_F0L + off);
                #pragma unroll
                for (int mt = 0; mt < 2; mt++) {
                    mma_bf16(d0[mt][2*ntp],   ah[mt][0], ah[mt][1], ah[mt][2], ah[mt][3], bh.x, bh.y);
                    mma_bf16(d0[mt][2*ntp],   ah[mt][0], ah[mt][1], ah[mt][2], ah[mt][3], bl.x, bl.y);
                    mma_bf16(d0[mt][2*ntp],   al[mt][0], al[mt][1], al[mt][2], al[mt][3], bh.x, bh.y);
                    mma_bf16(d0[mt][2*ntp+1], ah[mt][0], ah[mt][1], ah[mt][2], ah[mt][3], bh.z, bh.w);
                    mma_bf16(d0[mt][2*ntp+1], ah[mt][0], ah[mt][1], ah[mt][2], ah[mt][3], bl.z, bl.w);
                    mma_bf16(d0[mt][2*ntp+1], al[mt][0], al[mt][1], al[mt][2], al[mt][3], bh.z, bh.w);
                }
            }
        }

        // ---------- epilogue 0 in registers: bias+SiLU+split -> layer-1 A frags ----------
        // D frag of nt=2ks,2ks+1 repacks exactly into A frag of k-step ks.
        u32 ah1[2][4][4], al1[2][4][4];
        #pragma unroll
        for (int mt = 0; mt < 2; mt++) {
            #pragma unroll
            for (int ks = 0; ks < 4; ks++) {
                int n0 = 16 * ks + 2 * t4;
                float2 bbA = *(const float2*)(smem + SM_B0 + n0 * 4);
                float2 bbB = *(const float2*)(smem + SM_B0 + (n0 + 8) * 4);
                float v0 = fast_silu(d0[mt][2*ks][0] + bbA.x);
                float v1 = fast_silu(d0[mt][2*ks][1] + bbA.y);
                float v2 = fast_silu(d0[mt][2*ks][2] + bbA.x);
                float v3 = fast_silu(d0[mt][2*ks][3] + bbA.y);
                float w0 = fast_silu(d0[mt][2*ks+1][0] + bbB.x);
                float w1 = fast_silu(d0[mt][2*ks+1][1] + bbB.y);
                float w2 = fast_silu(d0[mt][2*ks+1][2] + bbB.x);
                float w3 = fast_silu(d0[mt][2*ks+1][3] + bbB.y);
                u32 h;
                h = pk(v0, v1); ah1[mt][ks][0] = h;
                al1[mt][ks][0] = pk(v0 - bf_lo(h), v1 - bf_hi(h));
                h = pk(v2, v3); ah1[mt][ks][1] = h;
                al1[mt][ks][1] = pk(v2 - bf_lo(h), v3 - bf_hi(h));
                h = pk(w0, w1); ah1[mt][ks][2] = h;
                al1[mt][ks][2] = pk(w0 - bf_lo(h), w1 - bf_hi(h));
                h = pk(w2, w3); ah1[mt][ks][3] = h;
                al1[mt][ks][3] = pk(w2 - bf_lo(h), w3 - bf_hi(h));
            }
        }

        // ---------- layer 1: A frags in registers ----------
        float d1[2][8][4];
        #pragma unroll
        for (int mt = 0; mt < 2; mt++)
            #pragma unroll
            for (int nt = 0; nt < 8; nt++)
                #pragma unroll
                for (int q = 0; q < 4; q++) d1[mt][nt][q] = 0.0f;

        #pragma unroll
        for (int ks = 0; ks < 4; ks++) {
            #pragma unroll
            for (int ntp = 0; ntp < 4; ntp++) {
                int off = ((ks * 4 + ntp) * 32 + lane) * 16;
                uint4 bh = *(const uint4*)(smem + SM_F1H + off);
                uint4 bl = *(const uint4*)(smem + SM_F1L + off);
                #pragma unroll
                for (int mt = 0; mt < 2; mt++) {
                    u32* ah = ah1[mt][ks];
                    u32* al = al1[mt][ks];
                    mma_bf16(d1[mt][2*ntp],   ah[0], ah[1], ah[2], ah[3], bh.x, bh.y);
                    mma_bf16(d1[mt][2*ntp],   ah[0], ah[1], ah[2], ah[3], bl.x, bl.y);
                    mma_bf16(d1[mt][2*ntp],   al[0], al[1], al[2], al[3], bh.x, bh.y);
                    mma_bf16(d1[mt][2*ntp+1], ah[0], ah[1], ah[2], ah[3], bh.z, bh.w);
                    mma_bf16(d1[mt][2*ntp+1], ah[0], ah[1], ah[2], ah[3], bl.z, bl.w);
                    mma_bf16(d1[mt][2*ntp+1], al[0], al[1], al[2], al[3], bh.z, bh.w);
                }
            }
        }

        // ---------- final: +b1, SiLU, dot Wout, quad reduce, sigmoid, store ----------
        {
            float outb = *((const float*)(smem + SM_BO));  // bout + BASE_LOGIT
            #pragma unroll
            for (int mt = 0; mt < 2; mt++) {
                float sT = 0.0f, sB = 0.0f;
                #pragma unroll
                for (int nt = 0; nt < 8; nt++) {
                    int n0 = nt * 8 + t4 * 2;
                    float2 bb = *(const float2*)(smem + SM_B1 + n0 * 4);
                    float2 ww = *(const float2*)(smem + SM_WO + n0 * 4);
                    sT = fmaf(fast_silu(d1[mt][nt][0] + bb.x), ww.x, sT);
                    sT = fmaf(fast_silu(d1[mt][nt][1] + bb.y), ww.y, sT);
                    sB = fmaf(fast_silu(d1[mt][nt][2] + bb.x), ww.x, sB);
                    sB = fmaf(fast_silu(d1[mt][nt][3] + bb.y), ww.y, sB);
                }
                sT += __shfl_xor_sync(0xffffffffu, sT, 1);
                sT += __shfl_xor_sync(0xffffffffu, sT, 2);
                sB += __shfl_xor_sync(0xffffffffu, sB, 1);
                sB += __shfl_xor_sync(0xffffffffu, sB, 2);

                int rlT = mt * 16 + g;
                int rlB = rlT + 8;
                int tT = __shfl_sync(0xffffffffu, t_c, rlT);
                int tB = __shfl_sync(0xffffffffu, t_c, rlB);

                if (t4 == 0) {
                    int pT = tile * M_TILE + rowA + rlT;
                    int pB = tile * M_TILE + rowA + rlB;
                    float thT = __fdividef(1.0f, 1.0f + __expf(-(sT + outb)));
                    float thB = __fdividef(1.0f, 1.0f + __expf(-(sB + outb)));
                    float oT = (tT == 0) ? (X_A0 * CSANMAX) : thT * CSANMAX;
                    float oB = (tB == 0) ? (X_A0 * CSANMAX) : thB * CSANMAX;
                    if (pT < n) outp[pT] = oT;
                    if (pB < n) outp[pB] = oB;
                }
            }
        }
        __syncwarp();   // WAR: all lanes done reading feature smem before next store

        // rotate prefetch
        t_c = t_n; r_c = r_n;
        #pragma unroll
        for (int q = 0; q < 8; q++) e_c[q] = e_n[q];
    }
}

extern "C" void kernel_launch(void* const* d_in, const int* in_sizes, int n_in,
                              void* d_out, int out_size)
{
    const int*   time_idx = (const int*)  d_in[0];
    const float* rho      = (const float*)d_in[1];
    const float* emb      = (const float*)d_in[2];
    const float* W0       = (const float*)d_in[3];
    const float* b0       = (const float*)d_in[4];
    const float* W1       = (const float*)d_in[5];
    const float* b1       = (const float*)d_in[6];
    const float* Wout     = (const float*)d_in[7];
    const float* bout     = (const float*)d_in[8];
    float* out = (float*)d_out;

    int n = in_sizes[0];
    int ntiles = (n + M_TILE - 1) / M_TILE;

    cudaFuncSetAttribute(slfm_hmma_kernel,
                         cudaFuncAttributeMaxDynamicSharedMemorySize, SM_TOTAL);
    int grid = ntiles < GRID_CTAS ? ntiles : GRID_CTAS;
    slfm_hmma_kernel<<<grid, TPB, SM_TOTAL>>>(time_idx, rho, emb, W0, b0, W1, b1,
                                              Wout, bout, out, n, ntiles);
}

// round 7
// speedup vs baseline: 4.5005x; 1.0916x over previous
#include <cuda_runtime.h>
#include <cuda_bf16.h>
#include <cstdint>
#include <math.h>

#define N_TIME   512
#define LATENT   32
#define HIDDEN   64
#define N_MODES  8
#define IN_DIM   49
#define X_A0     0.3f
#define CSANMAX  28700.0f
#define BASE_LOGIT (-0.8472978603872034f)
#define PI_F 3.14159265358979323846f

#define TPB       128
#define M_TILE    128
#define GRID_CTAS 444

#define ROW_STRIDE 72   // bf16 elems per feature row (144 B)

// ---- smem layout (bytes) ----
#define SM_AHI 0
#define SM_ALO (SM_AHI + M_TILE * ROW_STRIDE * 2)   // 18432
#define SM_F0H (SM_ALO + M_TILE * ROW_STRIDE * 2)   // 36864
#define SM_F0L (SM_F0H + 8192)
#define SM_F1H (SM_F0L + 8192)
#define SM_F1L (SM_F1H + 8192)
#define SM_B0  (SM_F1L + 8192)                      // 69632
#define SM_B1  (SM_B0 + 256)
#define SM_WO  (SM_B1 + 256)
#define SM_BO  (SM_WO + 256)
#define SM_TOTAL (SM_BO + 16)

typedef uint32_t u32;
typedef uint64_t u64;

__device__ __forceinline__ u32 smem_u32(const void* p) {
    u32 a;
    asm("{ .reg .u64 t; cvta.to.shared.u64 t, %1; cvt.u32.u64 %0, t; }"
        : "=r"(a) : "l"(p));
    return a;
}

// pack two fp32 -> bf16x2, first arg in LOW half
__device__ __forceinline__ u32 pk(float lo, float hi) {
    u32 r;
    asm("cvt.rn.bf16x2.f32 %0, %1, %2;" : "=r"(r) : "f"(hi), "f"(lo));
    return r;
}
__device__ __forceinline__ float bf_lo(u32 p) { return __uint_as_float(p << 16); }
__device__ __forceinline__ float bf_hi(u32 p) { return __uint_as_float(p & 0xffff0000u); }

__device__ __forceinline__ float tanh_ap(float x) {
    float y; asm("tanh.approx.f32 %0, %1;" : "=f"(y) : "f"(x)); return y;
}
// silu via tanh: 1 MUFU instead of 2
__device__ __forceinline__ float fast_silu(float v) {
    return v * fmaf(0.5f, tanh_ap(0.5f * v), 0.5f);
}

__device__ __forceinline__ void mma_bf16(float* d, u32 a0, u32 a1, u32 a2, u32 a3,
                                         u32 b0, u32 b1) {
    asm volatile("mma.sync.aligned.m16n8k16.row.col.f32.bf16.bf16.f32 "
                 "{%0,%1,%2,%3}, {%4,%5,%6,%7}, {%8,%9}, {%0,%1,%2,%3};"
                 : "+f"(d[0]), "+f"(d[1]), "+f"(d[2]), "+f"(d[3])
                 : "r"(a0), "r"(a1), "r"(a2), "r"(a3), "r"(b0), "r"(b1));
}

__device__ __forceinline__ void ldsm_x4(u32& r0, u32& r1, u32& r2, u32& r3, u32 addr) {
    asm volatile("ldmatrix.sync.aligned.m8n8.x4.shared.b16 {%0,%1,%2,%3}, [%4];"
                 : "=r"(r0), "=r"(r1), "=r"(r2), "=r"(r3) : "r"(addr));
}

// split 8 consecutive fp32 -> hi/lo bf16x2 quads
__device__ __forceinline__ void split8(const float* x, uint4& hv, uint4& lv) {
    u32 h[4], l[4];
    #pragma unroll
    for (int q = 0; q < 4; q++) {
        float a = x[2*q], b = x[2*q+1];
        u32 p = pk(a, b);
        h[q] = p;
        l[q] = pk(a - bf_lo(p), b - bf_hi(p));
    }
    hv = make_uint4(h[0], h[1], h[2], h[3]);
    lv = make_uint4(l[0], l[1], l[2], l[3]);
}

// build 49 features + zero-pad and store hi/lo rows to A smem (row = tid)
__device__ __forceinline__ void build_store_features(char* smem, int tid,
                                                     float r, const float4* e) {
    float xv[64];
    #pragma unroll
    for (int q = 0; q < 8; q++) {
        xv[4*q+0] = e[q].x; xv[4*q+1] = e[q].y;
        xv[4*q+2] = e[q].z; xv[4*q+3] = e[q].w;
    }
    xv[32] = r;
    float s1, c1;
    sincosf(PI_F * r, &s1, &c1);
    float ck = c1, sk = s1;
    xv[33] = ck; xv[41] = sk;
    #pragma unroll
    for (int k = 2; k <= N_MODES; k++) {
        float cn = fmaf(ck, c1, -sk * s1);
        float sn = fmaf(sk, c1,  ck * s1);
        ck = cn; sk = sn;
        xv[32 + k] = ck;
        xv[40 + k] = sk;
    }
    #pragma unroll
    for (int k = 49; k < 64; k++) xv[k] = 0.0f;

    #pragma unroll
    for (int gq = 0; gq < 8; gq++) {
        uint4 hv, lv;
        split8(xv + 8 * gq, hv, lv);
        int off = (tid * ROW_STRIDE + gq * 8) * 2;
        *(uint4*)(smem + SM_AHI + off) = hv;
        *(uint4*)(smem + SM_ALO + off) = lv;
    }
}

__global__ __launch_bounds__(TPB, 3)
void slfm_hmma_kernel(const int* __restrict__ time_idx,
                      const float* __restrict__ rho,
                      const float* __restrict__ emb,
                      const float* __restrict__ W0,
                      const float* __restrict__ b0g,
                      const float* __restrict__ W1,
                      const float* __restrict__ b1g,
                      const float* __restrict__ Woutg,
                      const float* __restrict__ boutg,
                      float* __restrict__ outp,
                      int n, int ntiles)
{
    extern __shared__ char smem[];
    const u32 sb = smem_u32(smem);
    const int tid  = threadIdx.x;
    const int lane = tid & 31;
    const int warp = tid >> 5;
    const int g    = lane >> 2;
    const int t4   = lane & 3;
    const int rowA = warp * 32;

    // ---- stage weight fragments, pair-packed uint4 per (ks, ntp, lane) ----
    for (int i = tid; i < 512; i += TPB) {
        int ks = i >> 7, ntp = (i >> 5) & 3, ln = i & 31;
        int gg = ln >> 2, tt = ln & 3;
        int k0 = ks * 16 + tt * 2;
        u32 a0h[4], a0l[4], a1h[4], a1l[4];
        #pragma unroll
        for (int sub = 0; sub < 2; sub++) {
            int nn = (ntp * 2 + sub) * 8 + gg;
            float w00 = (k0     < IN_DIM) ? W0[(k0    ) * HIDDEN + nn] : 0.0f;
            float w01 = (k0 + 1 < IN_DIM) ? W0[(k0 + 1) * HIDDEN + nn] : 0.0f;
            float w08 = (k0 + 8 < IN_DIM) ? W0[(k0 + 8) * HIDDEN + nn] : 0.0f;
            float w09 = (k0 + 9 < IN_DIM) ? W0[(k0 + 9) * HIDDEN + nn] : 0.0f;
            u32 h0 = pk(w00, w01);
            u32 h1 = pk(w08, w09);
            a0h[sub*2+0] = h0;
            a0h[sub*2+1] = h1;
            a0l[sub*2+0] = pk(w00 - bf_lo(h0), w01 - bf_hi(h0));
            a0l[sub*2+1] = pk(w08 - bf_lo(h1), w09 - bf_hi(h1));

            float v00 = W1[(k0    ) * HIDDEN + nn];
            float v01 = W1[(k0 + 1) * HIDDEN + nn];
            float v08 = W1[(k0 + 8) * HIDDEN + nn];
            float v09 = W1[(k0 + 9) * HIDDEN + nn];
            u32 p0 = pk(v00, v01);
            u32 p1 = pk(v08, v09);
            a1h[sub*2+0] = p0;
            a1h[sub*2+1] = p1;
            a1l[sub*2+0] = pk(v00 - bf_lo(p0), v01 - bf_hi(p0));
            a1l[sub*2+1] = pk(v08 - bf_lo(p1), v09 - bf_hi(p1));
        }
        int off = ((ks * 4 + ntp) * 32 + ln) * 16;
        *(uint4*)(smem + SM_F0H + off) = make_uint4(a0h[0], a0h[1], a0h[2], a0h[3]);
        *(uint4*)(smem + SM_F0L + off) = make_uint4(a0l[0], a0l[1], a0l[2], a0l[3]);
        *(uint4*)(smem + SM_F1H + off) = make_uint4(a1h[0], a1h[1], a1h[2], a1h[3]);
        *(uint4*)(smem + SM_F1L + off) = make_uint4(a1l[0], a1l[1], a1l[2], a1l[3]);
    }
    if (tid < HIDDEN) {
        ((float*)(smem + SM_B0))[tid] = b0g[tid];
        ((float*)(smem + SM_B1))[tid] = b1g[tid];
        ((float*)(smem + SM_WO))[tid] = Woutg[tid];
    }
    if (tid == 0) *((float*)(smem + SM_BO)) = boutg[0] + BASE_LOGIT;
    __syncthreads();

    // ldmatrix per-lane base addresses for feature A (hi / lo)
    const u32 aBaseHi = sb + SM_AHI +
        (u32)(((rowA + (lane & 15)) * ROW_STRIDE + (lane >> 4) * 8) * 2);
    const u32 aBaseLo = aBaseHi + (SM_ALO - SM_AHI);

    // ---- prologue: load + build features for first tile ----
    int tile = blockIdx.x;
    int t_c = 0;
    if (tile < ntiles) {
        int p = tile * M_TILE + tid;
        int ps = p < n ? p : n - 1;
        t_c = time_idx[ps];
        float r0 = rho[ps];
        int idx = t_c - 1;
        idx = idx < 0 ? 0 : (idx > N_TIME - 2 ? N_TIME - 2 : idx);
        float4 e0[8];
        const float4* er = (const float4*)(emb + (size_t)idx * LATENT);
        #pragma unroll
        for (int q = 0; q < 8; q++) e0[q] = er[q];
        build_store_features(smem, tid, r0, e0);
    }
    __syncwarp();

    for (; tile < ntiles; tile += GRID_CTAS) {
        // ---------- issue next-tile LDGs early (latency overlap) ----------
        int ntile2 = tile + GRID_CTAS;
        int   t_n = 0;
        float r_n = 0.0f;
        float4 e_n[8];
        if (ntile2 < ntiles) {
            int p = ntile2 * M_TILE + tid;
            int ps = p < n ? p : n - 1;
            t_n = time_idx[ps];
            r_n = rho[ps];
            int idx = t_n - 1;
            idx = idx < 0 ? 0 : (idx > N_TIME - 2 ? N_TIME - 2 : idx);
            const float4* er = (const float4*)(emb + (size_t)idx * LATENT);
            #pragma unroll
            for (int q = 0; q < 8; q++) e_n[q] = er[q];
        }

        // ---------- layer 0: A via ldmatrix, B via paired LDS.128 ----------
        float d0[2][8][4];
        #pragma unroll
        for (int mt = 0; mt < 2; mt++)
            #pragma unroll
            for (int nt = 0; nt < 8; nt++)
                #pragma unroll
                for (int q = 0; q < 4; q++) d0[mt][nt][q] = 0.0f;

        #pragma unroll
        for (int ks = 0; ks < 4; ks++) {
            u32 ah[2][4], al[2][4];
            #pragma unroll
            for (int mt = 0; mt < 2; mt++) {
                u32 moff = (u32)(mt * 16 * ROW_STRIDE * 2 + ks * 32);
                ldsm_x4(ah[mt][0], ah[mt][1], ah[mt][2], ah[mt][3], aBaseHi + moff);
                ldsm_x4(al[mt][0], al[mt][1], al[mt][2], al[mt][3], aBaseLo + moff);
            }
            #pragma unroll
            for (int ntp = 0; ntp < 4; ntp++) {
                int off = ((ks * 4 + ntp) * 32 + lane) * 16;
                uint4 bh = *(const uint4*)(smem + SM_F0H + off);
                uint4 bl = *(const uint4*)(smem + SM_F0L + off);
                #pragma unroll
                for (int mt = 0; mt < 2; mt++) {
                    mma_bf16(d0[mt][2*ntp],   ah[mt][0], ah[mt][1], ah[mt][2], ah[mt][3], bh.x, bh.y);
                    mma_bf16(d0[mt][2*ntp],   ah[mt][0], ah[mt][1], ah[mt][2], ah[mt][3], bl.x, bl.y);
                    mma_bf16(d0[mt][2*ntp],   al[mt][0], al[mt][1], al[mt][2], al[mt][3], bh.x, bh.y);
                    mma_bf16(d0[mt][2*ntp+1], ah[mt][0], ah[mt][1], ah[mt][2], ah[mt][3], bh.z, bh.w);
                    mma_bf16(d0[mt][2*ntp+1], ah[mt][0], ah[mt][1], ah[mt][2], ah[mt][3], bl.z, bl.w);
                    mma_bf16(d0[mt][2*ntp+1], al[mt][0], al[mt][1], al[mt][2], al[mt][3], bh.z, bh.w);
                }
            }
        }
        __syncwarp();   // warp's ldmatrix A reads complete -> A region dead

        // ---------- rebuild A smem for next tile (frees e_n registers) ----------
        if (ntile2 < ntiles) {
            build_store_features(smem, tid, r_n, e_n);
        }

        // ---------- epilogue 0 in registers: bias+SiLU+split -> layer-1 A frags ----------
        u32 ah1[2][4][4], al1[2][4][4];
        #pragma unroll
        for (int mt = 0; mt < 2; mt++) {
            #pragma unroll
            for (int ks = 0; ks < 4; ks++) {
                int n0 = 16 * ks + 2 * t4;
                float2 bbA = *(const float2*)(smem + SM_B0 + n0 * 4);
                float2 bbB = *(const float2*)(smem + SM_B0 + (n0 + 8) * 4);
                float v0 = fast_silu(d0[mt][2*ks][0] + bbA.x);
                float v1 = fast_silu(d0[mt][2*ks][1] + bbA.y);
                float v2 = fast_silu(d0[mt][2*ks][2] + bbA.x);
                float v3 = fast_silu(d0[mt][2*ks][3] + bbA.y);
                float w0 = fast_silu(d0[mt][2*ks+1][0] + bbB.x);
                float w1 = fast_silu(d0[mt][2*ks+1][1] + bbB.y);
                float w2 = fast_silu(d0[mt][2*ks+1][2] + bbB.x);
                float w3 = fast_silu(d0[mt][2*ks+1][3] + bbB.y);
                u32 h;
                h = pk(v0, v1); ah1[mt][ks][0] = h;
                al1[mt][ks][0] = pk(v0 - bf_lo(h), v1 - bf_hi(h));
                h = pk(v2, v3); ah1[mt][ks][1] = h;
                al1[mt][ks][1] = pk(v2 - bf_lo(h), v3 - bf_hi(h));
                h = pk(w0, w1); ah1[mt][ks][2] = h;
                al1[mt][ks][2] = pk(w0 - bf_lo(h), w1 - bf_hi(h));
                h = pk(w2, w3); ah1[mt][ks][3] = h;
                al1[mt][ks][3] = pk(w2 - bf_lo(h), w3 - bf_hi(h));
            }
        }

        // ---------- layer 1: A frags in registers ----------
        float d1[2][8][4];
        #pragma unroll
        for (int mt = 0; mt < 2; mt++)
            #pragma unroll
            for (int nt = 0; nt < 8; nt++)
                #pragma unroll
                for (int q = 0; q < 4; q++) d1[mt][nt][q] = 0.0f;

        #pragma unroll
        for (int ks = 0; ks < 4; ks++) {
            #pragma unroll
            for (int ntp = 0; ntp < 4; ntp++) {
                int off = ((ks * 4 + ntp) * 32 + lane) * 16;
                uint4 bh = *(const uint4*)(smem + SM_F1H + off);
                uint4 bl = *(const uint4*)(smem + SM_F1L + off);
                #pragma unroll
                for (int mt = 0; mt < 2; mt++) {
                    u32* ah = ah1[mt][ks];
                    u32* al = al1[mt][ks];
                    mma_bf16(d1[mt][2*ntp],   ah[0], ah[1], ah[2], ah[3], bh.x, bh.y);
                    mma_bf16(d1[mt][2*ntp],   ah[0], ah[1], ah[2], ah[3], bl.x, bl.y);
                    mma_bf16(d1[mt][2*ntp],   al[0], al[1], al[2], al[3], bh.x, bh.y);
                    mma_bf16(d1[mt][2*ntp+1], ah[0], ah[1], ah[2], ah[3], bh.z, bh.w);
                    mma_bf16(d1[mt][2*ntp+1], ah[0], ah[1], ah[2], ah[3], bl.z, bl.w);
                    mma_bf16(d1[mt][2*ntp+1], al[0], al[1], al[2], al[3], bh.z, bh.w);
                }
            }
        }

        // ---------- final: +b1, SiLU, dot Wout, quad reduce, sigmoid, store ----------
        {
            float outb = *((const float*)(smem + SM_BO));  // bout + BASE_LOGIT
            #pragma unroll
            for (int mt = 0; mt < 2; mt++) {
                float sT = 0.0f, sB = 0.0f;
                #pragma unroll
                for (int nt = 0; nt < 8; nt++) {
                    int n0 = nt * 8 + t4 * 2;
                    float2 bb = *(const float2*)(smem + SM_B1 + n0 * 4);
                    float2 ww = *(const float2*)(smem + SM_WO + n0 * 4);
                    sT = fmaf(fast_silu(d1[mt][nt][0] + bb.x), ww.x, sT);
                    sT = fmaf(fast_silu(d1[mt][nt][1] + bb.y), ww.y, sT);
                    sB = fmaf(fast_silu(d1[mt][nt][2] + bb.x), ww.x, sB);
                    sB = fmaf(fast_silu(d1[mt][nt][3] + bb.y), ww.y, sB);
                }
                sT += __shfl_xor_sync(0xffffffffu, sT, 1);
                sT += __shfl_xor_sync(0xffffffffu, sT, 2);
                sB += __shfl_xor_sync(0xffffffffu, sB, 1);
                sB += __shfl_xor_sync(0xffffffffu, sB, 2);

                int rlT = mt * 16 + g;
                int rlB = rlT + 8;
                int tT = __shfl_sync(0xffffffffu, t_c, rlT);
                int tB = __shfl_sync(0xffffffffu, t_c, rlB);

                if (t4 == 0) {
                    int pT = tile * M_TILE + rowA + rlT;
                    int pB = tile * M_TILE + rowA + rlB;
                    // exact-path sigmoid for the final output (no tanh.approx
                    // cancellation for small theta)
                    float thT = __fdividef(1.0f, 1.0f + __expf(-(sT + outb)));
                    float thB = __fdividef(1.0f, 1.0f + __expf(-(sB + outb)));
                    float oT = (tT == 0) ? (X_A0 * CSANMAX) : thT * CSANMAX;
                    float oB = (tB == 0) ? (X_A0 * CSANMAX) : thB * CSANMAX;
                    if (pT < n) outp[pT] = oT;
                    if (pB < n) outp[pB] = oB;
                }
            }
        }
        __syncwarp();
        t_c = t_n;
    }
}

extern "C" void kernel_launch(void* const* d_in, const int* in_sizes, int n_in,
                              void* d_out, int out_size)
{
    const int*   time_idx = (const int*)  d_in[0];
    const float* rho      = (const float*)d_in[1];
    const float* emb      = (const float*)d_in[2];
    const float* W0       = (const float*)d_in[3];
    const float* b0       = (const float*)d_in[4];
    const float* W1       = (const float*)d_in[5];
    const float* b1       = (const float*)d_in[6];
    const float* Wout     = (const float*)d_in[7];
    const float* bout     = (const float*)d_in[8];
    float* out = (float*)d_out;

    int n = in_sizes[0];
    int ntiles = (n + M_TILE - 1) / M_TILE;

    cudaFuncSetAttribute(slfm_hmma_kernel,
                         cudaFuncAttributeMaxDynamicSharedMemorySize, SM_TOTAL);
    int grid = ntiles < GRID_CTAS ? ntiles : GRID_CTAS;
    slfm_hmma_kernel<<<grid, TPB, SM_TOTAL>>>(time_idx, rho, emb, W0, b0, W1, b1,
                                              Wout, bout, out, n, ntiles);
}

// round 8
// speedup vs baseline: 6.1210x; 1.3601x over previous
#include <cuda_runtime.h>
#include <cuda_fp16.h>
#include <cstdint>
#include <math.h>

#define N_TIME   512
#define LATENT   32
#define HIDDEN   64
#define N_MODES  8
#define X_A0     0.3f
#define CSANMAX  28700.0f
#define BASE_LOGIT (-0.8472978603872034f)
#define PI_F 3.14159265358979323846f

#define TPB       128
#define M_TILE    128
#define GRID_CTAS 444

#define ROW_STRIDE 72   // bf16/fp16 elems per feature row (144 B; bank = (r+c) mod 8)

// ---- smem layout (bytes) ----
#define SM_AHI 0                                    // 128 rows x 144B (fp16 hi only)
#define SM_F0H (SM_AHI + M_TILE * ROW_STRIDE * 2)   // 18432, 3ks*4ntp*32*16 = 6144
#define SM_F0L (SM_F0H + 6144)
#define SM_F1H (SM_F0L + 6144)                      // 4ks -> 8192
#define SM_F1L (SM_F1H + 8192)
#define SM_B0  (SM_F1L + 8192)                      // 47104
#define SM_B1  (SM_B0 + 256)
#define SM_WO  (SM_B1 + 256)
#define SM_W48 (SM_WO + 256)                        // W0 row 48 (fp32, 64 floats)
#define SM_BO  (SM_W48 + 256)
#define SM_TOTAL (SM_BO + 16)                       // ~48.1 KB

typedef uint32_t u32;

#define HSCALE_DN 0x18001800u   // fp16x2 {2^-9, 2^-9}
#define RESID_SCALE 512.0f      // 2^9

__device__ __forceinline__ u32 smem_u32(const void* p) {
    u32 a;
    asm("{ .reg .u64 t; cvta.to.shared.u64 t, %1; cvt.u32.u64 %0, t; }"
        : "=r"(a) : "l"(p));
    return a;
}

// pack two fp32 -> fp16x2, first arg in LOW half
__device__ __forceinline__ u32 pk16(float lo, float hi) {
    u32 r;
    asm("cvt.rn.f16x2.f32 %0, %1, %2;" : "=r"(r) : "f"(hi), "f"(lo));
    return r;
}
__device__ __forceinline__ float h2f_lo(u32 p) {
    float f;
    asm("{ .reg .b16 l, h; mov.b32 {l, h}, %1; cvt.f32.f16 %0, l; }" : "=f"(f) : "r"(p));
    return f;
}
__device__ __forceinline__ float h2f_hi(u32 p) {
    float f;
    asm("{ .reg .b16 l, h; mov.b32 {l, h}, %1; cvt.f32.f16 %0, h; }" : "=f"(f) : "r"(p));
    return f;
}
// multiply packed fp16x2 by 2^-9
__device__ __forceinline__ u32 hdn9(u32 x) {
    u32 r;
    asm("mul.f16x2 %0, %1, %2;" : "=r"(r) : "r"(x), "r"(HSCALE_DN));
    return r;
}

__device__ __forceinline__ float tanh_ap(float x) {
    float y; asm("tanh.approx.f32 %0, %1;" : "=f"(y) : "f"(x)); return y;
}
__device__ __forceinline__ float fast_silu(float v) {
    return v * fmaf(0.5f, tanh_ap(0.5f * v), 0.5f);
}

__device__ __forceinline__ void mma_fp16(float* d, u32 a0, u32 a1, u32 a2, u32 a3,
                                         u32 b0, u32 b1) {
    asm volatile("mma.sync.aligned.m16n8k16.row.col.f32.f16.f16.f32 "
                 "{%0,%1,%2,%3}, {%4,%5,%6,%7}, {%8,%9}, {%0,%1,%2,%3};"
                 : "+f"(d[0]), "+f"(d[1]), "+f"(d[2]), "+f"(d[3])
                 : "r"(a0), "r"(a1), "r"(a2), "r"(a3), "r"(b0), "r"(b1));
}

__device__ __forceinline__ void ldsm_x4(u32& r0, u32& r1, u32& r2, u32& r3, u32 addr) {
    asm volatile("ldmatrix.sync.aligned.m8n8.x4.shared.b16 {%0,%1,%2,%3}, [%4];"
                 : "=r"(r0), "=r"(r1), "=r"(r2), "=r"(r3) : "r"(addr));
}

// build 48 stored features (k=0..47) + return sin(8*pi*rho) (k=48 handled scalar)
// feature order: [emb(32), rho, cos1..8 (33..40), sin1..7 (41..47)]
__device__ __forceinline__ float build_store_features(char* smem, int tid,
                                                      float r, const float4* e) {
    float xv[48];
    #pragma unroll
    for (int q = 0; q < 8; q++) {
        xv[4*q+0] = e[q].x; xv[4*q+1] = e[q].y;
        xv[4*q+2] = e[q].z; xv[4*q+3] = e[q].w;
    }
    xv[32] = r;
    float s1, c1;
    sincosf(PI_F * r, &s1, &c1);
    float ck = c1, sk = s1;
    xv[33] = ck; xv[41] = sk;
    float s8 = s1;
    #pragma unroll
    for (int k = 2; k <= N_MODES; k++) {
        float cn = fmaf(ck, c1, -sk * s1);
        float sn = fmaf(sk, c1,  ck * s1);
        ck = cn; sk = sn;
        xv[32 + k] = ck;
        if (k < 8) xv[40 + k] = sk;
        else       s8 = sk;
    }
    #pragma unroll
    for (int gq = 0; gq < 6; gq++) {
        const float* x = xv + 8 * gq;
        uint4 hv = make_uint4(pk16(x[0], x[1]), pk16(x[2], x[3]),
                              pk16(x[4], x[5]), pk16(x[6], x[7]));
        int off = (tid * ROW_STRIDE + gq * 8) * 2;
        *(uint4*)(smem + SM_AHI + off) = hv;
    }
    return s8;
}

__global__ __launch_bounds__(TPB, 3)
void slfm_hmma_kernel(const int* __restrict__ time_idx,
                      const float* __restrict__ rho,
                      const float* __restrict__ emb,
                      const float* __restrict__ W0,
                      const float* __restrict__ b0g,
                      const float* __restrict__ W1,
                      const float* __restrict__ b1g,
                      const float* __restrict__ Woutg,
                      const float* __restrict__ boutg,
                      float* __restrict__ outp,
                      int n, int ntiles)
{
    extern __shared__ char smem[];
    const u32 sb = smem_u32(smem);
    const int tid  = threadIdx.x;
    const int lane = tid & 31;
    const int warp = tid >> 5;
    const int g    = lane >> 2;
    const int t4   = lane & 3;
    const int rowA = warp * 32;

    // ---- stage fp16 hi + scaled-lo weight fragments ----
    // B-frag mapping: n = nt*8 + (lane>>2), k0 = ks*16 + (lane&3)*2;
    // uint4 slot packs nt=2ntp and nt=2ntp+1: {r0_nt0, r1_nt0, r0_nt1, r1_nt1}
    for (int i = tid; i < 512; i += TPB) {
        int ks = i >> 7, ntp = (i >> 5) & 3, ln = i & 31;
        int gg = ln >> 2, tt = ln & 3;
        int k0 = ks * 16 + tt * 2;

        // layer 1 (all ks 0..3)
        {
            u32 hh[4], llv[4];
            #pragma unroll
            for (int sub = 0; sub < 2; sub++) {
                int nn = (ntp * 2 + sub) * 8 + gg;
                float v00 = W1[(k0    ) * HIDDEN + nn];
                float v01 = W1[(k0 + 1) * HIDDEN + nn];
                float v08 = W1[(k0 + 8) * HIDDEN + nn];
                float v09 = W1[(k0 + 9) * HIDDEN + nn];
                u32 p0 = pk16(v00, v01);
                u32 p1 = pk16(v08, v09);
                hh[sub*2+0] = p0;
                hh[sub*2+1] = p1;
                llv[sub*2+0] = pk16((v00 - h2f_lo(p0)) * RESID_SCALE,
                                    (v01 - h2f_hi(p0)) * RESID_SCALE);
                llv[sub*2+1] = pk16((v08 - h2f_lo(p1)) * RESID_SCALE,
                                    (v09 - h2f_hi(p1)) * RESID_SCALE);
            }
            int off = ((ks * 4 + ntp) * 32 + ln) * 16;
            *(uint4*)(smem + SM_F1H + off) = make_uint4(hh[0], hh[1], hh[2], hh[3]);
            *(uint4*)(smem + SM_F1L + off) = make_uint4(llv[0], llv[1], llv[2], llv[3]);
        }
        // layer 0 (ks 0..2 only; k <= 47 < IN_DIM-1)
        if (ks < 3) {
            u32 hh[4], llv[4];
            #pragma unroll
            for (int sub = 0; sub < 2; sub++) {
                int nn = (ntp * 2 + sub) * 8 + gg;
                float w00 = W0[(k0    ) * HIDDEN + nn];
                float w01 = W0[(k0 + 1) * HIDDEN + nn];
                float w08 = W0[(k0 + 8) * HIDDEN + nn];
                float w09 = W0[(k0 + 9) * HIDDEN + nn];
                u32 p0 = pk16(w00, w01);
                u32 p1 = pk16(w08, w09);
                hh[sub*2+0] = p0;
                hh[sub*2+1] = p1;
                llv[sub*2+0] = pk16((w00 - h2f_lo(p0)) * RESID_SCALE,
                                    (w01 - h2f_hi(p0)) * RESID_SCALE);
                llv[sub*2+1] = pk16((w08 - h2f_lo(p1)) * RESID_SCALE,
                                    (w09 - h2f_hi(p1)) * RESID_SCALE);
            }
            int off = ((ks * 4 + ntp) * 32 + ln) * 16;
            *(uint4*)(smem + SM_F0H + off) = make_uint4(hh[0], hh[1], hh[2], hh[3]);
            *(uint4*)(smem + SM_F0L + off) = make_uint4(llv[0], llv[1], llv[2], llv[3]);
        }
    }
    if (tid < HIDDEN) {
        ((float*)(smem + SM_B0))[tid] = b0g[tid];
        ((float*)(smem + SM_B1))[tid] = b1g[tid];
        ((float*)(smem + SM_WO))[tid] = Woutg[tid];
        ((float*)(smem + SM_W48))[tid] = W0[48 * HIDDEN + tid];  // k=48 row (fp32)
    }
    if (tid == 0) *((float*)(smem + SM_BO)) = boutg[0] + BASE_LOGIT;
    __syncthreads();

    // ldmatrix per-lane base address for feature A (hi fp16)
    const u32 aBaseHi = sb + SM_AHI +
        (u32)(((rowA + (lane & 15)) * ROW_STRIDE + (lane >> 4) * 8) * 2);

    // ---- prologue: load + build first tile ----
    int tile = blockIdx.x;
    int t_c = 0;
    float s8_c = 0.0f;
    if (tile < ntiles) {
        int p = tile * M_TILE + tid;
        int ps = p < n ? p : n - 1;
        t_c = time_idx[ps];
        float r0 = rho[ps];
        int idx = t_c - 1;
        idx = idx < 0 ? 0 : (idx > N_TIME - 2 ? N_TIME - 2 : idx);
        float4 e0[8];
        const float4* er = (const float4*)(emb + (size_t)idx * LATENT);
        #pragma unroll
        for (int q = 0; q < 8; q++) e0[q] = er[q];
        s8_c = build_store_features(smem, tid, r0, e0);
    }
    __syncwarp();

    for (; tile < ntiles; tile += GRID_CTAS) {
        // ---------- issue next-tile LDGs early ----------
        int ntile2 = tile + GRID_CTAS;
        int   t_n = 0;
        float r_n = 0.0f;
        float4 e_n[8];
        if (ntile2 < ntiles) {
            int p = ntile2 * M_TILE + tid;
            int ps = p < n ? p : n - 1;
            t_n = time_idx[ps];
            r_n = rho[ps];
            int idx = t_n - 1;
            idx = idx < 0 ? 0 : (idx > N_TIME - 2 ? N_TIME - 2 : idx);
            const float4* er = (const float4*)(emb + (size_t)idx * LATENT);
            #pragma unroll
            for (int q = 0; q < 8; q++) e_n[q] = er[q];
        }

        // ---------- layer 0: 3 k-steps, 2-term fp16 ----------
        float d0[2][8][4];
        #pragma unroll
        for (int mt = 0; mt < 2; mt++)
            #pragma unroll
            for (int nt = 0; nt < 8; nt++)
                #pragma unroll
                for (int q = 0; q < 4; q++) d0[mt][nt][q] = 0.0f;

        #pragma unroll
        for (int ks = 0; ks < 3; ks++) {
            u32 ah[2][4], a2[2][4];
            #pragma unroll
            for (int mt = 0; mt < 2; mt++) {
                u32 moff = (u32)(mt * 16 * ROW_STRIDE * 2 + ks * 32);
                ldsm_x4(ah[mt][0], ah[mt][1], ah[mt][2], ah[mt][3], aBaseHi + moff);
                #pragma unroll
                for (int q = 0; q < 4; q++) a2[mt][q] = hdn9(ah[mt][q]);
            }
            #pragma unroll
            for (int ntp = 0; ntp < 4; ntp++) {
                int off = ((ks * 4 + ntp) * 32 + lane) * 16;
                uint4 bh = *(const uint4*)(smem + SM_F0H + off);
                uint4 bl = *(const uint4*)(smem + SM_F0L + off);
                #pragma unroll
                for (int mt = 0; mt < 2; mt++) {
                    mma_fp16(d0[mt][2*ntp],   ah[mt][0], ah[mt][1], ah[mt][2], ah[mt][3], bh.x, bh.y);
                    mma_fp16(d0[mt][2*ntp],   a2[mt][0], a2[mt][1], a2[mt][2], a2[mt][3], bl.x, bl.y);
                    mma_fp16(d0[mt][2*ntp+1], ah[mt][0], ah[mt][1], ah[mt][2], ah[mt][3], bh.z, bh.w);
                    mma_fp16(d0[mt][2*ntp+1], a2[mt][0], a2[mt][1], a2[mt][2], a2[mt][3], bl.z, bl.w);
                }
            }
        }
        __syncwarp();   // warp's A reads complete -> A region dead

        // ---------- rebuild A smem for next tile ----------
        float s8_n = 0.0f;
        if (ntile2 < ntiles) {
            s8_n = build_store_features(smem, tid, r_n, e_n);
        }

        // ---------- k=48 rank-1 fix: d0 += sin(8*pi*rho_row) * W0[48][col] ----------
        #pragma unroll
        for (int mt = 0; mt < 2; mt++) {
            float s8T = __shfl_sync(0xffffffffu, s8_c, mt * 16 + g);
            float s8B = __shfl_sync(0xffffffffu, s8_c, mt * 16 + g + 8);
            #pragma unroll
            for (int nt = 0; nt < 8; nt++) {
                int n0 = nt * 8 + t4 * 2;
                float2 w48 = *(const float2*)(smem + SM_W48 + n0 * 4);
                d0[mt][nt][0] = fmaf(s8T, w48.x, d0[mt][nt][0]);
                d0[mt][nt][1] = fmaf(s8T, w48.y, d0[mt][nt][1]);
                d0[mt][nt][2] = fmaf(s8B, w48.x, d0[mt][nt][2]);
                d0[mt][nt][3] = fmaf(s8B, w48.y, d0[mt][nt][3]);
            }
        }

        // ---------- epilogue 0: bias + SiLU -> fp16 layer-1 A frags (registers) ----------
        u32 ah1[2][4][4];
        #pragma unroll
        for (int mt = 0; mt < 2; mt++) {
            #pragma unroll
            for (int ks = 0; ks < 4; ks++) {
                int n0 = 16 * ks + 2 * t4;
                float2 bbA = *(const float2*)(smem + SM_B0 + n0 * 4);
                float2 bbB = *(const float2*)(smem + SM_B0 + (n0 + 8) * 4);
                float v0 = fast_silu(d0[mt][2*ks][0] + bbA.x);
                float v1 = fast_silu(d0[mt][2*ks][1] + bbA.y);
                float v2 = fast_silu(d0[mt][2*ks][2] + bbA.x);
                float v3 = fast_silu(d0[mt][2*ks][3] + bbA.y);
                float w0 = fast_silu(d0[mt][2*ks+1][0] + bbB.x);
                float w1 = fast_silu(d0[mt][2*ks+1][1] + bbB.y);
                float w2 = fast_silu(d0[mt][2*ks+1][2] + bbB.x);
                float w3 = fast_silu(d0[mt][2*ks+1][3] + bbB.y);
                ah1[mt][ks][0] = pk16(v0, v1);
                ah1[mt][ks][1] = pk16(v2, v3);
                ah1[mt][ks][2] = pk16(w0, w1);
                ah1[mt][ks][3] = pk16(w2, w3);
            }
        }

        // ---------- layer 1: 4 k-steps, 2-term fp16, A frags in regs ----------
        float d1[2][8][4];
        #pragma unroll
        for (int mt = 0; mt < 2; mt++)
            #pragma unroll
            for (int nt = 0; nt < 8; nt++)
                #pragma unroll
                for (int q = 0; q < 4; q++) d1[mt][nt][q] = 0.0f;

        #pragma unroll
        for (int ks = 0; ks < 4; ks++) {
            u32 a2[2][4];
            #pragma unroll
            for (int mt = 0; mt < 2; mt++)
                #pragma unroll
                for (int q = 0; q < 4; q++) a2[mt][q] = hdn9(ah1[mt][ks][q]);
            #pragma unroll
            for (int ntp = 0; ntp < 4; ntp++) {
                int off = ((ks * 4 + ntp) * 32 + lane) * 16;
                uint4 bh = *(const uint4*)(smem + SM_F1H + off);
                uint4 bl = *(const uint4*)(smem + SM_F1L + off);
                #pragma unroll
                for (int mt = 0; mt < 2; mt++) {
                    u32* ah = ah1[mt][ks];
                    mma_fp16(d1[mt][2*ntp],   ah[0], ah[1], ah[2], ah[3], bh.x, bh.y);
                    mma_fp16(d1[mt][2*ntp],   a2[mt][0], a2[mt][1], a2[mt][2], a2[mt][3], bl.x, bl.y);
                    mma_fp16(d1[mt][2*ntp+1], ah[0], ah[1], ah[2], ah[3], bh.z, bh.w);
                    mma_fp16(d1[mt][2*ntp+1], a2[mt][0], a2[mt][1], a2[mt][2], a2[mt][3], bl.z, bl.w);
                }
            }
        }

        // ---------- final: +b1, SiLU, dot Wout, quad reduce, sigmoid, store ----------
        {
            float outb = *((const float*)(smem + SM_BO));  // bout + BASE_LOGIT
            #pragma unroll
            for (int mt = 0; mt < 2; mt++) {
                float sT = 0.0f, sB = 0.0f;
                #pragma unroll
                for (int nt = 0; nt < 8; nt++) {
                    int n0 = nt * 8 + t4 * 2;
                    float2 bb = *(const float2*)(smem + SM_B1 + n0 * 4);
                    float2 ww = *(const float2*)(smem + SM_WO + n0 * 4);
                    sT = fmaf(fast_silu(d1[mt][nt][0] + bb.x), ww.x, sT);
                    sT = fmaf(fast_silu(d1[mt][nt][1] + bb.y), ww.y, sT);
                    sB = fmaf(fast_silu(d1[mt][nt][2] + bb.x), ww.x, sB);
                    sB = fmaf(fast_silu(d1[mt][nt][3] + bb.y), ww.y, sB);
                }
                sT += __shfl_xor_sync(0xffffffffu, sT, 1);
                sT += __shfl_xor_sync(0xffffffffu, sT, 2);
                sB += __shfl_xor_sync(0xffffffffu, sB, 1);
                sB += __shfl_xor_sync(0xffffffffu, sB, 2);

                int rlT = mt * 16 + g;
                int rlB = rlT + 8;
                int tT = __shfl_sync(0xffffffffu, t_c, rlT);
                int tB = __shfl_sync(0xffffffffu, t_c, rlB);

                if (t4 == 0) {
                    int pT = tile * M_TILE + rowA + rlT;
                    int pB = tile * M_TILE + rowA + rlB;
                    float thT = __fdividef(1.0f, 1.0f + __expf(-(sT + outb)));
                    float thB = __fdividef(1.0f, 1.0f + __expf(-(sB + outb)));
                    float oT = (tT == 0) ? (X_A0 * CSANMAX) : thT * CSANMAX;
                    float oB = (tB == 0) ? (X_A0 * CSANMAX) : thB * CSANMAX;
                    if (pT < n) outp[pT] = oT;
                    if (pB < n) outp[pB] = oB;
                }
            }
        }
        __syncwarp();
        t_c = t_n;
        s8_c = s8_n;
    }
}

extern "C" void kernel_launch(void* const* d_in, const int* in_sizes, int n_in,
                              void* d_out, int out_size)
{
    const int*   time_idx = (const int*)  d_in[0];
    const float* rho      = (const float*)d_in[1];
    const float* emb      = (const float*)d_in[2];
    const float* W0       = (const float*)d_in[3];
    const float* b0       = (const float*)d_in[4];
    const float* W1       = (const float*)d_in[5];
    const float* b1       = (const float*)d_in[6];
    const float* Wout     = (const float*)d_in[7];
    const float* bout     = (const float*)d_in[8];
    float* out = (float*)d_out;

    int n = in_sizes[0];
    int ntiles = (n + M_TILE - 1) / M_TILE;

    cudaFuncSetAttribute(slfm_hmma_kernel,
                         cudaFuncAttributeMaxDynamicSharedMemorySize, SM_TOTAL);
    int grid = ntiles < GRID_CTAS ? ntiles : GRID_CTAS;
    slfm_hmma_kernel<<<grid, TPB, SM_TOTAL>>>(time_idx, rho, emb, W0, b0, W1, b1,
                                              Wout, bout, out, n, ntiles);
}

// round 10
// speedup vs baseline: 7.0175x; 1.1465x over previous
#include <cuda_runtime.h>
#include <cuda_fp16.h>
#include <cstdint>
#include <math.h>

#define N_TIME   512
#define LATENT   32
#define HIDDEN   64
#define N_MODES  8
#define X_A0     0.3f
#define CSANMAX  28700.0f
#define BASE_LOGIT (-0.8472978603872034f)
#define PI_F 3.14159265358979323846f

#define TPB       128
#define M_TILE    128
#define GRID_CTAS 444

#define EMB_STRIDE_B  64   // bytes per emb row (exact 32 fp16); 16B-aligned for ldmatrix
#define TRIG_STRIDE_B 48   // bytes per trig row; 16B-aligned, conflict-free pattern

// ---- smem layout (bytes) ----
#define SM_EMB  0                          // 511 * 64 = 32704 -> pad 32768
#define SM_TRIG 32768                      // 128 * 48 = 6144
#define SM_F0H  (SM_TRIG + 6144)           // 38912, 3ks*4ntp*32*16 = 6144
#define SM_F0L  (SM_F0H + 6144)
#define SM_F1H  (SM_F0L + 6144)            // 4ks -> 8192
#define SM_F1L  (SM_F1H + 8192)
#define SM_B0   (SM_F1L + 8192)            // 67584
#define SM_B1   (SM_B0 + 256)
#define SM_WO   (SM_B1 + 256)
#define SM_W48  (SM_WO + 256)              // W0 row 48 (fp32)
#define SM_BO   (SM_W48 + 256)
#define SM_TOTAL (SM_BO + 16)              // 68624 (~67 KB) -> 3 CTAs/SM

typedef uint32_t u32;

#define HSCALE_DN 0x18001800u   // fp16x2 {2^-9, 2^-9}
#define RESID_SCALE 512.0f      // 2^9

__device__ __forceinline__ u32 smem_u32(const void* p) {
    u32 a;
    asm("{ .reg .u64 t; cvta.to.shared.u64 t, %1; cvt.u32.u64 %0, t; }"
        : "=r"(a) : "l"(p));
    return a;
}

// pack two fp32 -> fp16x2, first arg in LOW half
__device__ __forceinline__ u32 pk16(float lo, float hi) {
    u32 r;
    asm("cvt.rn.f16x2.f32 %0, %1, %2;" : "=r"(r) : "f"(hi), "f"(lo));
    return r;
}
__device__ __forceinline__ float h2f_lo(u32 p) {
    float f;
    asm("{ .reg .b16 l, h; mov.b32 {l, h}, %1; cvt.f32.f16 %0, l; }" : "=f"(f) : "r"(p));
    return f;
}
__device__ __forceinline__ float h2f_hi(u32 p) {
    float f;
    asm("{ .reg .b16 l, h; mov.b32 {l, h}, %1; cvt.f32.f16 %0, h; }" : "=f"(f) : "r"(p));
    return f;
}
__device__ __forceinline__ u32 hdn9(u32 x) {
    u32 r;
    asm("mul.f16x2 %0, %1, %2;" : "=r"(r) : "r"(x), "r"(HSCALE_DN));
    return r;
}

__device__ __forceinline__ float tanh_ap(float x) {
    float y; asm("tanh.approx.f32 %0, %1;" : "=f"(y) : "f"(x)); return y;
}
__device__ __forceinline__ float fast_silu(float v) {
    return v * fmaf(0.5f, tanh_ap(0.5f * v), 0.5f);
}

__device__ __forceinline__ void mma_fp16(float* d, u32 a0, u32 a1, u32 a2, u32 a3,
                                         u32 b0, u32 b1) {
    asm volatile("mma.sync.aligned.m16n8k16.row.col.f32.f16.f16.f32 "
                 "{%0,%1,%2,%3}, {%4,%5,%6,%7}, {%8,%9}, {%0,%1,%2,%3};"
                 : "+f"(d[0]), "+f"(d[1]), "+f"(d[2]), "+f"(d[3])
                 : "r"(a0), "r"(a1), "r"(a2), "r"(a3), "r"(b0), "r"(b1));
}

__device__ __forceinline__ void ldsm_x4(u32& r0, u32& r1, u32& r2, u32& r3, u32 addr) {
    asm volatile("ldmatrix.sync.aligned.m8n8.x4.shared.b16 {%0,%1,%2,%3}, [%4];"
                 : "=r"(r0), "=r"(r1), "=r"(r2), "=r"(r3) : "r"(addr));
}

// build trig features k=32..47 into trig smem row (tid), return sin(8*pi*rho)
// order: [rho, cos1..cos8, sin1..sin7]
__device__ __forceinline__ float build_trig(char* smem, int tid, float r) {
    float xv[16];
    xv[0] = r;
    float s1, c1;
    sincosf(PI_F * r, &s1, &c1);
    float ck = c1, sk = s1;
    xv[1] = ck; xv[9] = sk;
    float s8 = s1;
    #pragma unroll
    for (int k = 2; k <= N_MODES; k++) {
        float cn = fmaf(ck, c1, -sk * s1);
        float sn = fmaf(sk, c1,  ck * s1);
        ck = cn; sk = sn;
        xv[k] = ck;
        if (k < 8) xv[8 + k] = sk;
        else       s8 = sk;
    }
    uint4 v0 = make_uint4(pk16(xv[0], xv[1]), pk16(xv[2], xv[3]),
                          pk16(xv[4], xv[5]), pk16(xv[6], xv[7]));
    uint4 v1 = make_uint4(pk16(xv[8], xv[9]), pk16(xv[10], xv[11]),
                          pk16(xv[12], xv[13]), pk16(xv[14], xv[15]));
    char* rowp = smem + SM_TRIG + tid * TRIG_STRIDE_B;
    *(uint4*)(rowp)      = v0;
    *(uint4*)(rowp + 16) = v1;
    return s8;
}

__global__ __launch_bounds__(TPB, 3)
void slfm_hmma_kernel(const int* __restrict__ time_idx,
                      const float* __restrict__ rho,
                      const float* __restrict__ emb,
                      const float* __restrict__ W0,
                      const float* __restrict__ b0g,
                      const float* __restrict__ W1,
                      const float* __restrict__ b1g,
                      const float* __restrict__ Woutg,
                      const float* __restrict__ boutg,
                      float* __restrict__ outp,
                      int n, int ntiles)
{
    extern __shared__ char smem[];
    const u32 sb = smem_u32(smem);
    const int tid  = threadIdx.x;
    const int lane = tid & 31;
    const int warp = tid >> 5;
    const int g    = lane >> 2;
    const int t4   = lane & 3;
    const int rowA = warp * 32;

    // ---- stage emb table as fp16: row stride 64B, chunk q stored at q^(row&3) ----
    for (int i = tid; i < (N_TIME - 1) * 4; i += TPB) {
        int row = i >> 2, q = i & 3;
        const float4* e = (const float4*)(emb + row * LATENT) + q * 2;
        float4 e0 = e[0], e1 = e[1];
        uint4 v = make_uint4(pk16(e0.x, e0.y), pk16(e0.z, e0.w),
                             pk16(e1.x, e1.y), pk16(e1.z, e1.w));
        int qs = q ^ (row & 3);   // bank swizzle
        *(uint4*)(smem + SM_EMB + row * EMB_STRIDE_B + qs * 16) = v;
    }

    // ---- stage fp16 hi + scaled-lo weight fragments ----
    for (int i = tid; i < 512; i += TPB) {
        int ks = i >> 7, ntp = (i >> 5) & 3, ln = i & 31;
        int gg = ln >> 2, tt = ln & 3;
        int k0 = ks * 16 + tt * 2;

        {   // layer 1, all ks
            u32 hh[4], llv[4];
            #pragma unroll
            for (int sub = 0; sub < 2; sub++) {
                int nn = (ntp * 2 + sub) * 8 + gg;
                float v00 = W1[(k0    ) * HIDDEN + nn];
                float v01 = W1[(k0 + 1) * HIDDEN + nn];
                float v08 = W1[(k0 + 8) * HIDDEN + nn];
                float v09 = W1[(k0 + 9) * HIDDEN + nn];
                u32 p0 = pk16(v00, v01);
                u32 p1 = pk16(v08, v09);
                hh[sub*2+0] = p0;
                hh[sub*2+1] = p1;
                llv[sub*2+0] = pk16((v00 - h2f_lo(p0)) * RESID_SCALE,
                                    (v01 - h2f_hi(p0)) * RESID_SCALE);
                llv[sub*2+1] = pk16((v08 - h2f_lo(p1)) * RESID_SCALE,
                                    (v09 - h2f_hi(p1)) * RESID_SCALE);
            }
            int off = ((ks * 4 + ntp) * 32 + ln) * 16;
            *(uint4*)(smem + SM_F1H + off) = make_uint4(hh[0], hh[1], hh[2], hh[3]);
            *(uint4*)(smem + SM_F1L + off) = make_uint4(llv[0], llv[1], llv[2], llv[3]);
        }
        if (ks < 3) {   // layer 0, k = 0..47
            u32 hh[4], llv[4];
            #pragma unroll
            for (int sub = 0; sub < 2; sub++) {
                int nn = (ntp * 2 + sub) * 8 + gg;
                float w00 = W0[(k0    ) * HIDDEN + nn];
                float w01 = W0[(k0 + 1) * HIDDEN + nn];
                float w08 = W0[(k0 + 8) * HIDDEN + nn];
                float w09 = W0[(k0 + 9) * HIDDEN + nn];
                u32 p0 = pk16(w00, w01);
                u32 p1 = pk16(w08, w09);
                hh[sub*2+0] = p0;
                hh[sub*2+1] = p1;
                llv[sub*2+0] = pk16((w00 - h2f_lo(p0)) * RESID_SCALE,
                                    (w01 - h2f_hi(p0)) * RESID_SCALE);
                llv[sub*2+1] = pk16((w08 - h2f_lo(p1)) * RESID_SCALE,
                                    (w09 - h2f_hi(p1)) * RESID_SCALE);
            }
            int off = ((ks * 4 + ntp) * 32 + ln) * 16;
            *(uint4*)(smem + SM_F0H + off) = make_uint4(hh[0], hh[1], hh[2], hh[3]);
            *(uint4*)(smem + SM_F0L + off) = make_uint4(llv[0], llv[1], llv[2], llv[3]);
        }
    }
    if (tid < HIDDEN) {
        ((float*)(smem + SM_B0))[tid] = b0g[tid];
        ((float*)(smem + SM_B1))[tid] = b1g[tid];
        ((float*)(smem + SM_WO))[tid] = Woutg[tid];
        ((float*)(smem + SM_W48))[tid] = W0[48 * HIDDEN + tid];
    }
    if (tid == 0) *((float*)(smem + SM_BO)) = boutg[0] + BASE_LOGIT;

    // trig ldmatrix base (static per lane)
    const u32 trigBase = sb + SM_TRIG +
        (u32)((rowA + (lane & 15)) * TRIG_STRIDE_B + (lane >> 4) * 16);
    const int chunkSel = lane >> 4;   // 0 or 1

    // ---- prologue: first tile point data + trig ----
    int tile = blockIdx.x;
    int t_c = 0, idx_c = 0;
    float s8_c = 0.0f;
    if (tile < ntiles) {
        int p = tile * M_TILE + tid;
        int ps = p < n ? p : n - 1;
        t_c = time_idx[ps];
        float r0 = rho[ps];
        idx_c = t_c - 1;
        idx_c = idx_c < 0 ? 0 : (idx_c > N_TIME - 2 ? N_TIME - 2 : idx_c);
        s8_c = build_trig(smem, tid, r0);
    }
    __syncthreads();   // staging + trig visible

    for (; tile < ntiles; tile += GRID_CTAS) {
        // ---------- next-tile LDGs (tiny) ----------
        int ntile2 = tile + GRID_CTAS;
        int   t_n = 0, idx_n = 0;
        float r_n = 0.0f;
        if (ntile2 < ntiles) {
            int p = ntile2 * M_TILE + tid;
            int ps = p < n ? p : n - 1;
            t_n = time_idx[ps];
            r_n = rho[ps];
            idx_n = t_n - 1;
            idx_n = idx_n < 0 ? 0 : (idx_n > N_TIME - 2 ? N_TIME - 2 : idx_n);
        }

        // ---------- layer 0: A from emb table (ks 0,1) + trig (ks 2) ----------
        float d0[2][8][4];
        #pragma unroll
        for (int nt = 0; nt < 8; nt++) {
            int n0 = nt * 8 + t4 * 2;
            float2 bb = *(const float2*)(smem + SM_B0 + n0 * 4);
            #pragma unroll
            for (int mt = 0; mt < 2; mt++) {
                d0[mt][nt][0] = bb.x; d0[mt][nt][1] = bb.y;
                d0[mt][nt][2] = bb.x; d0[mt][nt][3] = bb.y;
            }
        }

        u32 ah[2][3][4];
        #pragma unroll
        for (int mt = 0; mt < 2; mt++) {
            int idxr = __shfl_sync(0xffffffffu, idx_c, (lane & 15) | (mt << 4));
            u32 rbase = sb + SM_EMB + (u32)idxr * EMB_STRIDE_B;
            int sw = idxr & 3;
            u32 a0 = rbase + (u32)((chunkSel ^ sw) * 16);           // chunks 0,1
            u32 a1 = rbase + (u32)(((chunkSel + 2) ^ sw) * 16);     // chunks 2,3
            ldsm_x4(ah[mt][0][0], ah[mt][0][1], ah[mt][0][2], ah[mt][0][3], a0);
            ldsm_x4(ah[mt][1][0], ah[mt][1][1], ah[mt][1][2], ah[mt][1][3], a1);
            u32 tb = trigBase + (u32)(mt * 16 * TRIG_STRIDE_B);
            ldsm_x4(ah[mt][2][0], ah[mt][2][1], ah[mt][2][2], ah[mt][2][3], tb);
        }

        #pragma unroll
        for (int ks = 0; ks < 3; ks++) {
            u32 a2[2][4];
            #pragma unroll
            for (int mt = 0; mt < 2; mt++)
                #pragma unroll
                for (int q = 0; q < 4; q++) a2[mt][q] = hdn9(ah[mt][ks][q]);
            #pragma unroll
            for (int ntp = 0; ntp < 4; ntp++) {
                int off = ((ks * 4 + ntp) * 32 + lane) * 16;
                uint4 bh = *(const uint4*)(smem + SM_F0H + off);
                uint4 bl = *(const uint4*)(smem + SM_F0L + off);
                #pragma unroll
                for (int mt = 0; mt < 2; mt++) {
                    u32* a = ah[mt][ks];
                    mma_fp16(d0[mt][2*ntp],   a[0], a[1], a[2], a[3], bh.x, bh.y);
                    mma_fp16(d0[mt][2*ntp],   a2[mt][0], a2[mt][1], a2[mt][2], a2[mt][3], bl.x, bl.y);
                    mma_fp16(d0[mt][2*ntp+1], a[0], a[1], a[2], a[3], bh.z, bh.w);
                    mma_fp16(d0[mt][2*ntp+1], a2[mt][0], a2[mt][1], a2[mt][2], a2[mt][3], bl.z, bl.w);
                }
            }
        }
        __syncwarp();   // warp's trig reads complete -> trig rows dead

        // ---------- rebuild trig for next tile ----------
        float s8_n = 0.0f;
        if (ntile2 < ntiles) s8_n = build_trig(smem, tid, r_n);

        // ---------- k=48 rank-1 fix: d0 += sin(8*pi*rho_row) * W0[48][col] ----------
        #pragma unroll
        for (int mt = 0; mt < 2; mt++) {
            float s8T = __shfl_sync(0xffffffffu, s8_c, mt * 16 + g);
            float s8B = __shfl_sync(0xffffffffu, s8_c, mt * 16 + g + 8);
            #pragma unroll
            for (int nt = 0; nt < 8; nt++) {
                int n0 = nt * 8 + t4 * 2;
                float2 w48 = *(const float2*)(smem + SM_W48 + n0 * 4);
                d0[mt][nt][0] = fmaf(s8T, w48.x, d0[mt][nt][0]);
                d0[mt][nt][1] = fmaf(s8T, w48.y, d0[mt][nt][1]);
                d0[mt][nt][2] = fmaf(s8B, w48.x, d0[mt][nt][2]);
                d0[mt][nt][3] = fmaf(s8B, w48.y, d0[mt][nt][3]);
            }
        }

        // ---------- epilogue 0: SiLU -> fp16 layer-1 A frags ----------
        u32 ah1[2][4][4];
        #pragma unroll
        for (int mt = 0; mt < 2; mt++) {
            #pragma unroll
            for (int ks = 0; ks < 4; ks++) {
                float v0 = fast_silu(d0[mt][2*ks][0]);
                float v1 = fast_silu(d0[mt][2*ks][1]);
                float v2 = fast_silu(d0[mt][2*ks][2]);
                float v3 = fast_silu(d0[mt][2*ks][3]);
                float w0 = fast_silu(d0[mt][2*ks+1][0]);
                float w1 = fast_silu(d0[mt][2*ks+1][1]);
                float w2 = fast_silu(d0[mt][2*ks+1][2]);
                float w3 = fast_silu(d0[mt][2*ks+1][3]);
                ah1[mt][ks][0] = pk16(v0, v1);
                ah1[mt][ks][1] = pk16(v2, v3);
                ah1[mt][ks][2] = pk16(w0, w1);
                ah1[mt][ks][3] = pk16(w2, w3);
            }
        }

        // ---------- layer 1 (d1 init with b1) ----------
        float d1[2][8][4];
        #pragma unroll
        for (int nt = 0; nt < 8; nt++) {
            int n0 = nt * 8 + t4 * 2;
            float2 bb = *(const float2*)(smem + SM_B1 + n0 * 4);
            #pragma unroll
            for (int mt = 0; mt < 2; mt++) {
                d1[mt][nt][0] = bb.x; d1[mt][nt][1] = bb.y;
                d1[mt][nt][2] = bb.x; d1[mt][nt][3] = bb.y;
            }
        }

        #pragma unroll
        for (int ks = 0; ks < 4; ks++) {
            u32 a2[2][4];
            #pragma unroll
            for (int mt = 0; mt < 2; mt++)
                #pragma unroll
                for (int q = 0; q < 4; q++) a2[mt][q] = hdn9(ah1[mt][ks][q]);
            #pragma unroll
            for (int ntp = 0; ntp < 4; ntp++) {
                int off = ((ks * 4 + ntp) * 32 + lane) * 16;
                uint4 bh = *(const uint4*)(smem + SM_F1H + off);
                uint4 bl = *(const uint4*)(smem + SM_F1L + off);
                #pragma unroll
                for (int mt = 0; mt < 2; mt++) {
                    u32* a = ah1[mt][ks];
                    mma_fp16(d1[mt][2*ntp],   a[0], a[1], a[2], a[3], bh.x, bh.y);
                    mma_fp16(d1[mt][2*ntp],   a2[mt][0], a2[mt][1], a2[mt][2], a2[mt][3], bl.x, bl.y);
                    mma_fp16(d1[mt][2*ntp+1], a[0], a[1], a[2], a[3], bh.z, bh.w);
                    mma_fp16(d1[mt][2*ntp+1], a2[mt][0], a2[mt][1], a2[mt][2], a2[mt][3], bl.z, bl.w);
                }
            }
        }

        // ---------- final: SiLU, dot Wout, quad reduce, sigmoid, store ----------
        {
            float outb = *((const float*)(smem + SM_BO));  // bout + BASE_LOGIT
            #pragma unroll
            for (int mt = 0; mt < 2; mt++) {
                float sT = 0.0f, sB = 0.0f;
                #pragma unroll
                for (int nt = 0; nt < 8; nt++) {
                    int n0 = nt * 8 + t4 * 2;
                    float2 ww = *(const float2*)(smem + SM_WO + n0 * 4);
                    sT = fmaf(fast_silu(d1[mt][nt][0]), ww.x, sT);
                    sT = fmaf(fast_silu(d1[mt][nt][1]), ww.y, sT);
                    sB = fmaf(fast_silu(d1[mt][nt][2]), ww.x, sB);
                    sB = fmaf(fast_silu(d1[mt][nt][3]), ww.y, sB);
                }
                sT += __shfl_xor_sync(0xffffffffu, sT, 1);
                sT += __shfl_xor_sync(0xffffffffu, sT, 2);
                sB += __shfl_xor_sync(0xffffffffu, sB, 1);
                sB += __shfl_xor_sync(0xffffffffu, sB, 2);

                int rlT = mt * 16 + g;
                int rlB = rlT + 8;
                int tT = __shfl_sync(0xffffffffu, t_c, rlT);
                int tB = __shfl_sync(0xffffffffu, t_c, rlB);

                if (t4 == 0) {
                    int pT = tile * M_TILE + rowA + rlT;
                    int pB = tile * M_TILE + rowA + rlB;
                    float thT = __fdividef(1.0f, 1.0f + __expf(-(sT + outb)));
                    float thB = __fdividef(1.0f, 1.0f + __expf(-(sB + outb)));
                    float oT = (tT == 0) ? (X_A0 * CSANMAX) : thT * CSANMAX;
                    float oB = (tB == 0) ? (X_A0 * CSANMAX) : thB * CSANMAX;
                    if (pT < n) outp[pT] = oT;
                    if (pB < n) outp[pB] = oB;
                }
            }
        }
        __syncwarp();
        t_c = t_n;
        idx_c = idx_n;
        s8_c = s8_n;
    }
}

extern "C" void kernel_launch(void* const* d_in, const int* in_sizes, int n_in,
                              void* d_out, int out_size)
{
    const int*   time_idx = (const int*)  d_in[0];
    const float* rho      = (const float*)d_in[1];
    const float* emb      = (const float*)d_in[2];
    const float* W0       = (const float*)d_in[3];
    const float* b0       = (const float*)d_in[4];
    const float* W1       = (const float*)d_in[5];
    const float* b1       = (const float*)d_in[6];
    const float* Wout     = (const float*)d_in[7];
    const float* bout     = (const float*)d_in[8];
    float* out = (float*)d_out;

    int n = in_sizes[0];
    int ntiles = (n + M_TILE - 1) / M_TILE;

    cudaFuncSetAttribute(slfm_hmma_kernel,
                         cudaFuncAttributeMaxDynamicSharedMemorySize, SM_TOTAL);
    int grid = ntiles < GRID_CTAS ? ntiles : GRID_CTAS;
    slfm_hmma_kernel<<<grid, TPB, SM_TOTAL>>>(time_idx, rho, emb, W0, b0, W1, b1,
                                              Wout, bout, out, n, ntiles);
}

// round 11
// speedup vs baseline: 9.2489x; 1.3180x over previous
#include <cuda_runtime.h>
#include <cuda_fp16.h>
#include <cstdint>
#include <math.h>

#define N_TIME   512
#define LATENT   32
#define HIDDEN   64
#define N_MODES  8
#define X_A0     0.3f
#define CSANMAX  28700.0f
#define BASE_LOGIT (-0.8472978603872034f)
#define PI_F 3.14159265358979323846f

#define TPB       128
#define M_TILE    128
#define GRID_CTAS 592

#define EMB_STRIDE_B  64   // bytes per emb row (32 fp16); 16B-aligned for ldmatrix
#define TRIG_STRIDE_B 48   // bytes per trig row; 16B-aligned, conflict-free

// ---- smem layout (bytes) ----
#define SM_EMB  0                          // 511 * 64 -> pad 32768
#define SM_TRIG 32768                      // 128 * 48 = 6144
#define SM_F0H  (SM_TRIG + 6144)           // 38912, 3ks*4ntp*32*16 = 6144
#define SM_F1H  (SM_F0H + 6144)            // 45056, 4ks -> 8192
#define SM_B0   (SM_F1H + 8192)            // 53248
#define SM_B1   (SM_B0 + 256)
#define SM_WO   (SM_B1 + 256)
#define SM_W48  (SM_WO + 256)              // W0 row 48 (fp32)
#define SM_BO   (SM_W48 + 256)
#define SM_TOTAL (SM_BO + 16)              // 54288 (~53 KB) -> 4 CTAs/SM

typedef uint32_t u32;

__device__ __forceinline__ u32 smem_u32(const void* p) {
    u32 a;
    asm("{ .reg .u64 t; cvta.to.shared.u64 t, %1; cvt.u32.u64 %0, t; }"
        : "=r"(a) : "l"(p));
    return a;
}

// pack two fp32 -> fp16x2, first arg in LOW half
__device__ __forceinline__ u32 pk16(float lo, float hi) {
    u32 r;
    asm("cvt.rn.f16x2.f32 %0, %1, %2;" : "=r"(r) : "f"(hi), "f"(lo));
    return r;
}

__device__ __forceinline__ float tanh_ap(float x) {
    float y; asm("tanh.approx.f32 %0, %1;" : "=f"(y) : "f"(x)); return y;
}
__device__ __forceinline__ float fast_silu(float v) {
    return v * fmaf(0.5f, tanh_ap(0.5f * v), 0.5f);
}

__device__ __forceinline__ void mma_fp16(float* d, u32 a0, u32 a1, u32 a2, u32 a3,
                                         u32 b0, u32 b1) {
    asm volatile("mma.sync.aligned.m16n8k16.row.col.f32.f16.f16.f32 "
                 "{%0,%1,%2,%3}, {%4,%5,%6,%7}, {%8,%9}, {%0,%1,%2,%3};"
                 : "+f"(d[0]), "+f"(d[1]), "+f"(d[2]), "+f"(d[3])
                 : "r"(a0), "r"(a1), "r"(a2), "r"(a3), "r"(b0), "r"(b1));
}

__device__ __forceinline__ void ldsm_x4(u32& r0, u32& r1, u32& r2, u32& r3, u32 addr) {
    asm volatile("ldmatrix.sync.aligned.m8n8.x4.shared.b16 {%0,%1,%2,%3}, [%4];"
                 : "=r"(r0), "=r"(r1), "=r"(r2), "=r"(r3) : "r"(addr));
}

// build trig features k=32..47 into trig smem row (tid), return sin(8*pi*rho)
// order: [rho, cos1..cos8, sin1..sin7]
__device__ __forceinline__ float build_trig(char* smem, int tid, float r) {
    float xv[16];
    xv[0] = r;
    float s1, c1;
    sincosf(PI_F * r, &s1, &c1);
    float ck = c1, sk = s1;
    xv[1] = ck; xv[9] = sk;
    float s8 = s1;
    #pragma unroll
    for (int k = 2; k <= N_MODES; k++) {
        float cn = fmaf(ck, c1, -sk * s1);
        float sn = fmaf(sk, c1,  ck * s1);
        ck = cn; sk = sn;
        xv[k] = ck;
        if (k < 8) xv[8 + k] = sk;
        else       s8 = sk;
    }
    uint4 v0 = make_uint4(pk16(xv[0], xv[1]), pk16(xv[2], xv[3]),
                          pk16(xv[4], xv[5]), pk16(xv[6], xv[7]));
    uint4 v1 = make_uint4(pk16(xv[8], xv[9]), pk16(xv[10], xv[11]),
                          pk16(xv[12], xv[13]), pk16(xv[14], xv[15]));
    char* rowp = smem + SM_TRIG + tid * TRIG_STRIDE_B;
    *(uint4*)(rowp)      = v0;
    *(uint4*)(rowp + 16) = v1;
    return s8;
}

__global__ __launch_bounds__(TPB, 4)
void slfm_hmma_kernel(const int* __restrict__ time_idx,
                      const float* __restrict__ rho,
                      const float* __restrict__ emb,
                      const float* __restrict__ W0,
                      const float* __restrict__ b0g,
                      const float* __restrict__ W1,
                      const float* __restrict__ b1g,
                      const float* __restrict__ Woutg,
                      const float* __restrict__ boutg,
                      float* __restrict__ outp,
                      int n, int ntiles)
{
    extern __shared__ char smem[];
    const u32 sb = smem_u32(smem);
    const int tid  = threadIdx.x;
    const int lane = tid & 31;
    const int warp = tid >> 5;
    const int g    = lane >> 2;
    const int t4   = lane & 3;
    const int rowA = warp * 32;

    // ---- stage emb table as fp16: row stride 64B, chunk q stored at q^(row&3) ----
    for (int i = tid; i < (N_TIME - 1) * 4; i += TPB) {
        int row = i >> 2, q = i & 3;
        const float4* e = (const float4*)(emb + row * LATENT) + q * 2;
        float4 e0 = e[0], e1 = e[1];
        uint4 v = make_uint4(pk16(e0.x, e0.y), pk16(e0.z, e0.w),
                             pk16(e1.x, e1.y), pk16(e1.z, e1.w));
        int qs = q ^ (row & 3);   // bank swizzle
        *(uint4*)(smem + SM_EMB + row * EMB_STRIDE_B + qs * 16) = v;
    }

    // ---- stage fp16 weight fragments (hi only) ----
    for (int i = tid; i < 512; i += TPB) {
        int ks = i >> 7, ntp = (i >> 5) & 3, ln = i & 31;
        int gg = ln >> 2, tt = ln & 3;
        int k0 = ks * 16 + tt * 2;

        {   // layer 1, all ks
            u32 hh[4];
            #pragma unroll
            for (int sub = 0; sub < 2; sub++) {
                int nn = (ntp * 2 + sub) * 8 + gg;
                hh[sub*2+0] = pk16(W1[(k0    ) * HIDDEN + nn],
                                   W1[(k0 + 1) * HIDDEN + nn]);
                hh[sub*2+1] = pk16(W1[(k0 + 8) * HIDDEN + nn],
                                   W1[(k0 + 9) * HIDDEN + nn]);
            }
            int off = ((ks * 4 + ntp) * 32 + ln) * 16;
            *(uint4*)(smem + SM_F1H + off) = make_uint4(hh[0], hh[1], hh[2], hh[3]);
        }
        if (ks < 3) {   // layer 0, k = 0..47
            u32 hh[4];
            #pragma unroll
            for (int sub = 0; sub < 2; sub++) {
                int nn = (ntp * 2 + sub) * 8 + gg;
                hh[sub*2+0] = pk16(W0[(k0    ) * HIDDEN + nn],
                                   W0[(k0 + 1) * HIDDEN + nn]);
                hh[sub*2+1] = pk16(W0[(k0 + 8) * HIDDEN + nn],
                                   W0[(k0 + 9) * HIDDEN + nn]);
            }
            int off = ((ks * 4 + ntp) * 32 + ln) * 16;
            *(uint4*)(smem + SM_F0H + off) = make_uint4(hh[0], hh[1], hh[2], hh[3]);
        }
    }
    if (tid < HIDDEN) {
        ((float*)(smem + SM_B0))[tid] = b0g[tid];
        ((float*)(smem + SM_B1))[tid] = b1g[tid];
        ((float*)(smem + SM_WO))[tid] = Woutg[tid];
        ((float*)(smem + SM_W48))[tid] = W0[48 * HIDDEN + tid];
    }
    if (tid == 0) *((float*)(smem + SM_BO)) = boutg[0] + BASE_LOGIT;

    // trig ldmatrix base (static per lane)
    const u32 trigBase = sb + SM_TRIG +
        (u32)((rowA + (lane & 15)) * TRIG_STRIDE_B + (lane >> 4) * 16);
    const int chunkSel = lane >> 4;   // 0 or 1

    // ---- prologue: first tile point data + trig ----
    int tile = blockIdx.x;
    int t_c = 0, idx_c = 0;
    float s8_c = 0.0f;
    if (tile < ntiles) {
        int p = tile * M_TILE + tid;
        int ps = p < n ? p : n - 1;
        t_c = time_idx[ps];
        float r0 = rho[ps];
        idx_c = t_c - 1;
        idx_c = idx_c < 0 ? 0 : (idx_c > N_TIME - 2 ? N_TIME - 2 : idx_c);
        s8_c = build_trig(smem, tid, r0);
    }
    __syncthreads();   // staging + trig visible

    for (; tile < ntiles; tile += GRID_CTAS) {
        // ---------- next-tile LDGs (tiny) ----------
        int ntile2 = tile + GRID_CTAS;
        int   t_n = 0, idx_n = 0;
        float r_n = 0.0f;
        if (ntile2 < ntiles) {
            int p = ntile2 * M_TILE + tid;
            int ps = p < n ? p : n - 1;
            t_n = time_idx[ps];
            r_n = rho[ps];
            idx_n = t_n - 1;
            idx_n = idx_n < 0 ? 0 : (idx_n > N_TIME - 2 ? N_TIME - 2 : idx_n);
        }

        // ---------- layer 0: A from emb table (ks 0,1) + trig (ks 2) ----------
        float d0[2][8][4];
        #pragma unroll
        for (int nt = 0; nt < 8; nt++) {
            int n0 = nt * 8 + t4 * 2;
            float2 bb = *(const float2*)(smem + SM_B0 + n0 * 4);
            #pragma unroll
            for (int mt = 0; mt < 2; mt++) {
                d0[mt][nt][0] = bb.x; d0[mt][nt][1] = bb.y;
                d0[mt][nt][2] = bb.x; d0[mt][nt][3] = bb.y;
            }
        }

        u32 ah[2][3][4];
        #pragma unroll
        for (int mt = 0; mt < 2; mt++) {
            int idxr = __shfl_sync(0xffffffffu, idx_c, (lane & 15) | (mt << 4));
            u32 rbase = sb + SM_EMB + (u32)idxr * EMB_STRIDE_B;
            int sw = idxr & 3;
            u32 a0 = rbase + (u32)((chunkSel ^ sw) * 16);           // chunks 0,1
            u32 a1 = rbase + (u32)(((chunkSel + 2) ^ sw) * 16);     // chunks 2,3
            ldsm_x4(ah[mt][0][0], ah[mt][0][1], ah[mt][0][2], ah[mt][0][3], a0);
            ldsm_x4(ah[mt][1][0], ah[mt][1][1], ah[mt][1][2], ah[mt][1][3], a1);
            u32 tb = trigBase + (u32)(mt * 16 * TRIG_STRIDE_B);
            ldsm_x4(ah[mt][2][0], ah[mt][2][1], ah[mt][2][2], ah[mt][2][3], tb);
        }

        #pragma unroll
        for (int ks = 0; ks < 3; ks++) {
            #pragma unroll
            for (int ntp = 0; ntp < 4; ntp++) {
                int off = ((ks * 4 + ntp) * 32 + lane) * 16;
                uint4 bh = *(const uint4*)(smem + SM_F0H + off);
                #pragma unroll
                for (int mt = 0; mt < 2; mt++) {
                    u32* a = ah[mt][ks];
                    mma_fp16(d0[mt][2*ntp],   a[0], a[1], a[2], a[3], bh.x, bh.y);
                    mma_fp16(d0[mt][2*ntp+1], a[0], a[1], a[2], a[3], bh.z, bh.w);
                }
            }
        }
        __syncwarp();   // warp's trig reads complete -> trig rows dead

        // ---------- rebuild trig for next tile ----------
        float s8_n = 0.0f;
        if (ntile2 < ntiles) s8_n = build_trig(smem, tid, r_n);

        // ---------- k=48 rank-1 fix: d0 += sin(8*pi*rho_row) * W0[48][col] ----------
        #pragma unroll
        for (int mt = 0; mt < 2; mt++) {
            float s8T = __shfl_sync(0xffffffffu, s8_c, mt * 16 + g);
            float s8B = __shfl_sync(0xffffffffu, s8_c, mt * 16 + g + 8);
            #pragma unroll
            for (int nt = 0; nt < 8; nt++) {
                int n0 = nt * 8 + t4 * 2;
                float2 w48 = *(const float2*)(smem + SM_W48 + n0 * 4);
                d0[mt][nt][0] = fmaf(s8T, w48.x, d0[mt][nt][0]);
                d0[mt][nt][1] = fmaf(s8T, w48.y, d0[mt][nt][1]);
                d0[mt][nt][2] = fmaf(s8B, w48.x, d0[mt][nt][2]);
                d0[mt][nt][3] = fmaf(s8B, w48.y, d0[mt][nt][3]);
            }
        }

        // ---------- epilogue 0: SiLU -> fp16 layer-1 A frags ----------
        u32 ah1[2][4][4];
        #pragma unroll
        for (int mt = 0; mt < 2; mt++) {
            #pragma unroll
            for (int ks = 0; ks < 4; ks++) {
                float v0 = fast_silu(d0[mt][2*ks][0]);
                float v1 = fast_silu(d0[mt][2*ks][1]);
                float v2 = fast_silu(d0[mt][2*ks][2]);
                float v3 = fast_silu(d0[mt][2*ks][3]);
                float w0 = fast_silu(d0[mt][2*ks+1][0]);
                float w1 = fast_silu(d0[mt][2*ks+1][1]);
                float w2 = fast_silu(d0[mt][2*ks+1][2]);
                float w3 = fast_silu(d0[mt][2*ks+1][3]);
                ah1[mt][ks][0] = pk16(v0, v1);
                ah1[mt][ks][1] = pk16(v2, v3);
                ah1[mt][ks][2] = pk16(w0, w1);
                ah1[mt][ks][3] = pk16(w2, w3);
            }
        }

        // ---------- layer 1 (d1 init with b1) ----------
        float d1[2][8][4];
        #pragma unroll
        for (int nt = 0; nt < 8; nt++) {
            int n0 = nt * 8 + t4 * 2;
            float2 bb = *(const float2*)(smem + SM_B1 + n0 * 4);
            #pragma unroll
            for (int mt = 0; mt < 2; mt++) {
                d1[mt][nt][0] = bb.x; d1[mt][nt][1] = bb.y;
                d1[mt][nt][2] = bb.x; d1[mt][nt][3] = bb.y;
            }
        }

        #pragma unroll
        for (int ks = 0; ks < 4; ks++) {
            #pragma unroll
            for (int ntp = 0; ntp < 4; ntp++) {
                int off = ((ks * 4 + ntp) * 32 + lane) * 16;
                uint4 bh = *(const uint4*)(smem + SM_F1H + off);
                #pragma unroll
                for (int mt = 0; mt < 2; mt++) {
                    u32* a = ah1[mt][ks];
                    mma_fp16(d1[mt][2*ntp],   a[0], a[1], a[2], a[3], bh.x, bh.y);
                    mma_fp16(d1[mt][2*ntp+1], a[0], a[1], a[2], a[3], bh.z, bh.w);
                }
            }
        }

        // ---------- final: SiLU, dot Wout, quad reduce, sigmoid, store ----------
        {
            float outb = *((const float*)(smem + SM_BO));  // bout + BASE_LOGIT
            #pragma unroll
            for (int mt = 0; mt < 2; mt++) {
                float sT = 0.0f, sB = 0.0f;
                #pragma unroll
                for (int nt = 0; nt < 8; nt++) {
                    int n0 = nt * 8 + t4 * 2;
                    float2 ww = *(const float2*)(smem + SM_WO + n0 * 4);
                    sT = fmaf(fast_silu(d1[mt][nt][0]), ww.x, sT);
                    sT = fmaf(fast_silu(d1[mt][nt][1]), ww.y, sT);
                    sB = fmaf(fast_silu(d1[mt][nt][2]), ww.x, sB);
                    sB = fmaf(fast_silu(d1[mt][nt][3]), ww.y, sB);
                }
                sT += __shfl_xor_sync(0xffffffffu, sT, 1);
                sT += __shfl_xor_sync(0xffffffffu, sT, 2);
                sB += __shfl_xor_sync(0xffffffffu, sB, 1);
                sB += __shfl_xor_sync(0xffffffffu, sB, 2);

                int rlT = mt * 16 + g;
                int rlB = rlT + 8;
                int tT = __shfl_sync(0xffffffffu, t_c, rlT);
                int tB = __shfl_sync(0xffffffffu, t_c, rlB);

                if (t4 == 0) {
                    int pT = tile * M_TILE + rowA + rlT;
                    int pB = tile * M_TILE + rowA + rlB;
                    float thT = __fdividef(1.0f, 1.0f + __expf(-(sT + outb)));
                    float thB = __fdividef(1.0f, 1.0f + __expf(-(sB + outb)));
                    float oT = (tT == 0) ? (X_A0 * CSANMAX) : thT * CSANMAX;
                    float oB = (tB == 0) ? (X_A0 * CSANMAX) : thB * CSANMAX;
                    if (pT < n) outp[pT] = oT;
                    if (pB < n) outp[pB] = oB;
                }
            }
        }
        __syncwarp();
        t_c = t_n;
        idx_c = idx_n;
        s8_c = s8_n;
    }
}

extern "C" void kernel_launch(void* const* d_in, const int* in_sizes, int n_in,
                              void* d_out, int out_size)
{
    const int*   time_idx = (const int*)  d_in[0];
    const float* rho      = (const float*)d_in[1];
    const float* emb      = (const float*)d_in[2];
    const float* W0       = (const float*)d_in[3];
    const float* b0       = (const float*)d_in[4];
    const float* W1       = (const float*)d_in[5];
    const float* b1       = (const float*)d_in[6];
    const float* Wout     = (const float*)d_in[7];
    const float* bout     = (const float*)d_in[8];
    float* out = (float*)d_out;

    int n = in_sizes[0];
    int ntiles = (n + M_TILE - 1) / M_TILE;

    cudaFuncSetAttribute(slfm_hmma_kernel,
                         cudaFuncAttributeMaxDynamicSharedMemorySize, SM_TOTAL);
    int grid = ntiles < GRID_CTAS ? ntiles : GRID_CTAS;
    slfm_hmma_kernel<<<grid, TPB, SM_TOTAL>>>(time_idx, rho, emb, W0, b0, W1, b1,
                                              Wout, bout, out, n, ntiles);
}

// round 12
// speedup vs baseline: 9.2721x; 1.0025x over previous
#include <cuda_runtime.h>
#include <cuda_fp16.h>
#include <cstdint>
#include <math.h>

#define N_TIME   512
#define LATENT   32
#define HIDDEN   64
#define N_MODES  8
#define X_A0     0.3f
#define CSANMAX  28700.0f
#define BASE_LOGIT (-0.8472978603872034f)
#define PI_F 3.14159265358979323846f

#define TPB       128
#define M_TILE    128
#define GRID_CTAS 592

#define EMB_STRIDE_B  64   // bytes per emb row (32 fp16); 16B-aligned for ldmatrix
#define TRIG_STRIDE_B 48   // bytes per trig row; 16B-aligned, conflict-free

// ---- smem layout (bytes) ----
#define SM_EMB  0                          // 511 * 64 -> pad 32768
#define SM_TRIG 32768                      // 128 * 48 = 6144
#define SM_F0H  (SM_TRIG + 6144)           // 38912, 3ks*4ntp*32*16 = 6144
#define SM_F1H  (SM_F0H + 6144)            // 45056, 4ks -> 8192
#define SM_B0   (SM_F1H + 8192)            // 53248
#define SM_B1   (SM_B0 + 256)
#define SM_WO   (SM_B1 + 256)
#define SM_W48  (SM_WO + 256)              // W0 row 48 (fp32)
#define SM_BO   (SM_W48 + 256)
#define SM_TOTAL (SM_BO + 16)              // 54288 (~53 KB) -> 4 CTAs/SM

typedef uint32_t u32;

#define HALF2_HALF 0x38003800u   // fp16x2 {0.5, 0.5}

__device__ __forceinline__ u32 smem_u32(const void* p) {
    u32 a;
    asm("{ .reg .u64 t; cvta.to.shared.u64 t, %1; cvt.u32.u64 %0, t; }"
        : "=r"(a) : "l"(p));
    return a;
}

// pack two fp32 -> fp16x2, first arg in LOW half
__device__ __forceinline__ u32 pk16(float lo, float hi) {
    u32 r;
    asm("cvt.rn.f16x2.f32 %0, %1, %2;" : "=r"(r) : "f"(hi), "f"(lo));
    return r;
}
__device__ __forceinline__ float h2f_lo(u32 p) {
    float f;
    asm("{ .reg .b16 l, h; mov.b32 {l, h}, %1; cvt.f32.f16 %0, l; }" : "=f"(f) : "r"(p));
    return f;
}
__device__ __forceinline__ float h2f_hi(u32 p) {
    float f;
    asm("{ .reg .b16 l, h; mov.b32 {l, h}, %1; cvt.f32.f16 %0, h; }" : "=f"(f) : "r"(p));
    return f;
}

__device__ __forceinline__ float tanh_ap(float x) {
    float y; asm("tanh.approx.f32 %0, %1;" : "=f"(y) : "f"(x)); return y;
}
__device__ __forceinline__ float fast_silu(float v) {
    return v * fmaf(0.5f, tanh_ap(0.5f * v), 0.5f);
}

// packed silu on fp16x2: h = x * (0.5*tanh(0.5x) + 0.5). ONE MUFU per 2 elems.
__device__ __forceinline__ u32 silu_pk(u32 hx) {
    u32 t, th, s, r;
    asm("mul.f16x2 %0, %1, %2;" : "=r"(t)  : "r"(hx), "r"(HALF2_HALF));
    asm("tanh.approx.f16x2 %0, %1;" : "=r"(th) : "r"(t));
    asm("fma.rn.f16x2 %0, %1, %2, %3;" : "=r"(s) : "r"(th), "r"(HALF2_HALF), "r"(HALF2_HALF));
    asm("mul.f16x2 %0, %1, %2;" : "=r"(r) : "r"(hx), "r"(s));
    return r;
}

__device__ __forceinline__ void mma_fp16(float* d, u32 a0, u32 a1, u32 a2, u32 a3,
                                         u32 b0, u32 b1) {
    asm volatile("mma.sync.aligned.m16n8k16.row.col.f32.f16.f16.f32 "
                 "{%0,%1,%2,%3}, {%4,%5,%6,%7}, {%8,%9}, {%0,%1,%2,%3};"
                 : "+f"(d[0]), "+f"(d[1]), "+f"(d[2]), "+f"(d[3])
                 : "r"(a0), "r"(a1), "r"(a2), "r"(a3), "r"(b0), "r"(b1));
}

__device__ __forceinline__ void ldsm_x4(u32& r0, u32& r1, u32& r2, u32& r3, u32 addr) {
    asm volatile("ldmatrix.sync.aligned.m8n8.x4.shared.b16 {%0,%1,%2,%3}, [%4];"
                 : "=r"(r0), "=r"(r1), "=r"(r2), "=r"(r3) : "r"(addr));
}

// build trig features k=32..47 into trig smem row (tid), return sin(8*pi*rho)
// order: [rho, cos1..cos8, sin1..sin7]
__device__ __forceinline__ float build_trig(char* smem, int tid, float r) {
    float xv[16];
    xv[0] = r;
    float s1, c1;
    sincosf(PI_F * r, &s1, &c1);
    float ck = c1, sk = s1;
    xv[1] = ck; xv[9] = sk;
    float s8 = s1;
    #pragma unroll
    for (int k = 2; k <= N_MODES; k++) {
        float cn = fmaf(ck, c1, -sk * s1);
        float sn = fmaf(sk, c1,  ck * s1);
        ck = cn; sk = sn;
        xv[k] = ck;
        if (k < 8) xv[8 + k] = sk;
        else       s8 = sk;
    }
    uint4 v0 = make_uint4(pk16(xv[0], xv[1]), pk16(xv[2], xv[3]),
                          pk16(xv[4], xv[5]), pk16(xv[6], xv[7]));
    uint4 v1 = make_uint4(pk16(xv[8], xv[9]), pk16(xv[10], xv[11]),
                          pk16(xv[12], xv[13]), pk16(xv[14], xv[15]));
    char* rowp = smem + SM_TRIG + tid * TRIG_STRIDE_B;
    *(uint4*)(rowp)      = v0;
    *(uint4*)(rowp + 16) = v1;
    return s8;
}

__global__ __launch_bounds__(TPB, 4)
void slfm_hmma_kernel(const int* __restrict__ time_idx,
                      const float* __restrict__ rho,
                      const float* __restrict__ emb,
                      const float* __restrict__ W0,
                      const float* __restrict__ b0g,
                      const float* __restrict__ W1,
                      const float* __restrict__ b1g,
                      const float* __restrict__ Woutg,
                      const float* __restrict__ boutg,
                      float* __restrict__ outp,
                      int n, int ntiles)
{
    extern __shared__ char smem[];
    const u32 sb = smem_u32(smem);
    const int tid  = threadIdx.x;
    const int lane = tid & 31;
    const int warp = tid >> 5;
    const int g    = lane >> 2;
    const int t4   = lane & 3;
    const int rowA = warp * 32;

    // ---- stage emb table as fp16: row stride 64B, chunk q stored at q^(row&3) ----
    for (int i = tid; i < (N_TIME - 1) * 4; i += TPB) {
        int row = i >> 2, q = i & 3;
        const float4* e = (const float4*)(emb + row * LATENT) + q * 2;
        float4 e0 = e[0], e1 = e[1];
        uint4 v = make_uint4(pk16(e0.x, e0.y), pk16(e0.z, e0.w),
                             pk16(e1.x, e1.y), pk16(e1.z, e1.w));
        int qs = q ^ (row & 3);   // bank swizzle
        *(uint4*)(smem + SM_EMB + row * EMB_STRIDE_B + qs * 16) = v;
    }

    // ---- stage fp16 weight fragments (hi only) ----
    for (int i = tid; i < 512; i += TPB) {
        int ks = i >> 7, ntp = (i >> 5) & 3, ln = i & 31;
        int gg = ln >> 2, tt = ln & 3;
        int k0 = ks * 16 + tt * 2;

        {   // layer 1, all ks
            u32 hh[4];
            #pragma unroll
            for (int sub = 0; sub < 2; sub++) {
                int nn = (ntp * 2 + sub) * 8 + gg;
                hh[sub*2+0] = pk16(W1[(k0    ) * HIDDEN + nn],
                                   W1[(k0 + 1) * HIDDEN + nn]);
                hh[sub*2+1] = pk16(W1[(k0 + 8) * HIDDEN + nn],
                                   W1[(k0 + 9) * HIDDEN + nn]);
            }
            int off = ((ks * 4 + ntp) * 32 + ln) * 16;
            *(uint4*)(smem + SM_F1H + off) = make_uint4(hh[0], hh[1], hh[2], hh[3]);
        }
        if (ks < 3) {   // layer 0, k = 0..47
            u32 hh[4];
            #pragma unroll
            for (int sub = 0; sub < 2; sub++) {
                int nn = (ntp * 2 + sub) * 8 + gg;
                hh[sub*2+0] = pk16(W0[(k0    ) * HIDDEN + nn],
                                   W0[(k0 + 1) * HIDDEN + nn]);
                hh[sub*2+1] = pk16(W0[(k0 + 8) * HIDDEN + nn],
                                   W0[(k0 + 9) * HIDDEN + nn]);
            }
            int off = ((ks * 4 + ntp) * 32 + ln) * 16;
            *(uint4*)(smem + SM_F0H + off) = make_uint4(hh[0], hh[1], hh[2], hh[3]);
        }
    }
    if (tid < HIDDEN) {
        ((float*)(smem + SM_B0))[tid] = b0g[tid];
        ((float*)(smem + SM_B1))[tid] = b1g[tid];
        ((float*)(smem + SM_WO))[tid] = Woutg[tid];
        ((float*)(smem + SM_W48))[tid] = W0[48 * HIDDEN + tid];
    }
    if (tid == 0) *((float*)(smem + SM_BO)) = boutg[0] + BASE_LOGIT;

    // trig ldmatrix base (static per lane)
    const u32 trigBase = sb + SM_TRIG +
        (u32)((rowA + (lane & 15)) * TRIG_STRIDE_B + (lane >> 4) * 16);
    const int chunkSel = lane >> 4;   // 0 or 1

    // ---- prologue: first tile point data + trig ----
    int tile = blockIdx.x;
    int t_c = 0, idx_c = 0;
    float s8_c = 0.0f;
    if (tile < ntiles) {
        int p = tile * M_TILE + tid;
        int ps = p < n ? p : n - 1;
        t_c = time_idx[ps];
        float r0 = rho[ps];
        idx_c = t_c - 1;
        idx_c = idx_c < 0 ? 0 : (idx_c > N_TIME - 2 ? N_TIME - 2 : idx_c);
        s8_c = build_trig(smem, tid, r0);
    }
    __syncthreads();   // staging + trig visible

    for (; tile < ntiles; tile += GRID_CTAS) {
        // ---------- next-tile LDGs (tiny) ----------
        int ntile2 = tile + GRID_CTAS;
        int   t_n = 0, idx_n = 0;
        float r_n = 0.0f;
        if (ntile2 < ntiles) {
            int p = ntile2 * M_TILE + tid;
            int ps = p < n ? p : n - 1;
            t_n = time_idx[ps];
            r_n = rho[ps];
            idx_n = t_n - 1;
            idx_n = idx_n < 0 ? 0 : (idx_n > N_TIME - 2 ? N_TIME - 2 : idx_n);
        }

        // ---------- layer 0: A from emb table (ks 0,1) + trig (ks 2) ----------
        float d0[2][8][4];
        #pragma unroll
        for (int nt = 0; nt < 8; nt++) {
            int n0 = nt * 8 + t4 * 2;
            float2 bb = *(const float2*)(smem + SM_B0 + n0 * 4);
            #pragma unroll
            for (int mt = 0; mt < 2; mt++) {
                d0[mt][nt][0] = bb.x; d0[mt][nt][1] = bb.y;
                d0[mt][nt][2] = bb.x; d0[mt][nt][3] = bb.y;
            }
        }

        u32 ah[2][3][4];
        #pragma unroll
        for (int mt = 0; mt < 2; mt++) {
            int idxr = __shfl_sync(0xffffffffu, idx_c, (lane & 15) | (mt << 4));
            u32 rbase = sb + SM_EMB + (u32)idxr * EMB_STRIDE_B;
            int sw = idxr & 3;
            u32 a0 = rbase + (u32)((chunkSel ^ sw) * 16);           // chunks 0,1
            u32 a1 = rbase + (u32)(((chunkSel + 2) ^ sw) * 16);     // chunks 2,3
            ldsm_x4(ah[mt][0][0], ah[mt][0][1], ah[mt][0][2], ah[mt][0][3], a0);
            ldsm_x4(ah[mt][1][0], ah[mt][1][1], ah[mt][1][2], ah[mt][1][3], a1);
            u32 tb = trigBase + (u32)(mt * 16 * TRIG_STRIDE_B);
            ldsm_x4(ah[mt][2][0], ah[mt][2][1], ah[mt][2][2], ah[mt][2][3], tb);
        }

        #pragma unroll
        for (int ks = 0; ks < 3; ks++) {
            #pragma unroll
            for (int ntp = 0; ntp < 4; ntp++) {
                int off = ((ks * 4 + ntp) * 32 + lane) * 16;
                uint4 bh = *(const uint4*)(smem + SM_F0H + off);
                #pragma unroll
                for (int mt = 0; mt < 2; mt++) {
                    u32* a = ah[mt][ks];
                    mma_fp16(d0[mt][2*ntp],   a[0], a[1], a[2], a[3], bh.x, bh.y);
                    mma_fp16(d0[mt][2*ntp+1], a[0], a[1], a[2], a[3], bh.z, bh.w);
                }
            }
        }
        __syncwarp();   // warp's trig reads complete -> trig rows dead

        // ---------- rebuild trig for next tile ----------
        float s8_n = 0.0f;
        if (ntile2 < ntiles) s8_n = build_trig(smem, tid, r_n);

        // ---------- k=48 rank-1 fix: d0 += sin(8*pi*rho_row) * W0[48][col] ----------
        #pragma unroll
        for (int mt = 0; mt < 2; mt++) {
            float s8T = __shfl_sync(0xffffffffu, s8_c, mt * 16 + g);
            float s8B = __shfl_sync(0xffffffffu, s8_c, mt * 16 + g + 8);
            #pragma unroll
            for (int nt = 0; nt < 8; nt++) {
                int n0 = nt * 8 + t4 * 2;
                float2 w48 = *(const float2*)(smem + SM_W48 + n0 * 4);
                d0[mt][nt][0] = fmaf(s8T, w48.x, d0[mt][nt][0]);
                d0[mt][nt][1] = fmaf(s8T, w48.y, d0[mt][nt][1]);
                d0[mt][nt][2] = fmaf(s8B, w48.x, d0[mt][nt][2]);
                d0[mt][nt][3] = fmaf(s8B, w48.y, d0[mt][nt][3]);
            }
        }

        // ---------- epilogue 0: pack -> PACKED silu (f16x2) -> layer-1 A frags ----------
        u32 ah1[2][4][4];
        #pragma unroll
        for (int mt = 0; mt < 2; mt++) {
            #pragma unroll
            for (int ks = 0; ks < 4; ks++) {
                ah1[mt][ks][0] = silu_pk(pk16(d0[mt][2*ks][0],   d0[mt][2*ks][1]));
                ah1[mt][ks][1] = silu_pk(pk16(d0[mt][2*ks][2],   d0[mt][2*ks][3]));
                ah1[mt][ks][2] = silu_pk(pk16(d0[mt][2*ks+1][0], d0[mt][2*ks+1][1]));
                ah1[mt][ks][3] = silu_pk(pk16(d0[mt][2*ks+1][2], d0[mt][2*ks+1][3]));
            }
        }

        // ---------- layer 1 (d1 init with b1) ----------
        float d1[2][8][4];
        #pragma unroll
        for (int nt = 0; nt < 8; nt++) {
            int n0 = nt * 8 + t4 * 2;
            float2 bb = *(const float2*)(smem + SM_B1 + n0 * 4);
            #pragma unroll
            for (int mt = 0; mt < 2; mt++) {
                d1[mt][nt][0] = bb.x; d1[mt][nt][1] = bb.y;
                d1[mt][nt][2] = bb.x; d1[mt][nt][3] = bb.y;
            }
        }

        #pragma unroll
        for (int ks = 0; ks < 4; ks++) {
            #pragma unroll
            for (int ntp = 0; ntp < 4; ntp++) {
                int off = ((ks * 4 + ntp) * 32 + lane) * 16;
                uint4 bh = *(const uint4*)(smem + SM_F1H + off);
                #pragma unroll
                for (int mt = 0; mt < 2; mt++) {
                    u32* a = ah1[mt][ks];
                    mma_fp16(d1[mt][2*ntp],   a[0], a[1], a[2], a[3], bh.x, bh.y);
                    mma_fp16(d1[mt][2*ntp+1], a[0], a[1], a[2], a[3], bh.z, bh.w);
                }
            }
        }

        // ---------- final: PACKED silu, unpack, fp32 dot Wout, reduce, sigmoid ----------
        {
            float outb = *((const float*)(smem + SM_BO));  // bout + BASE_LOGIT
            #pragma unroll
            for (int mt = 0; mt < 2; mt++) {
                float sT = 0.0f, sB = 0.0f;
                #pragma unroll
                for (int nt = 0; nt < 8; nt++) {
                    int n0 = nt * 8 + t4 * 2;
                    float2 ww = *(const float2*)(smem + SM_WO + n0 * 4);
                    u32 hpT = silu_pk(pk16(d1[mt][nt][0], d1[mt][nt][1]));
                    u32 hpB = silu_pk(pk16(d1[mt][nt][2], d1[mt][nt][3]));
                    sT = fmaf(h2f_lo(hpT), ww.x, sT);
                    sT = fmaf(h2f_hi(hpT), ww.y, sT);
                    sB = fmaf(h2f_lo(hpB), ww.x, sB);
                    sB = fmaf(h2f_hi(hpB), ww.y, sB);
                }
                sT += __shfl_xor_sync(0xffffffffu, sT, 1);
                sT += __shfl_xor_sync(0xffffffffu, sT, 2);
                sB += __shfl_xor_sync(0xffffffffu, sB, 1);
                sB += __shfl_xor_sync(0xffffffffu, sB, 2);

                int rlT = mt * 16 + g;
                int rlB = rlT + 8;
                int tT = __shfl_sync(0xffffffffu, t_c, rlT);
                int tB = __shfl_sync(0xffffffffu, t_c, rlB);

                if (t4 == 0) {
                    int pT = tile * M_TILE + rowA + rlT;
                    int pB = tile * M_TILE + rowA + rlB;
                    float thT = __fdividef(1.0f, 1.0f + __expf(-(sT + outb)));
                    float thB = __fdividef(1.0f, 1.0f + __expf(-(sB + outb)));
                    float oT = (tT == 0) ? (X_A0 * CSANMAX) : thT * CSANMAX;
                    float oB = (tB == 0) ? (X_A0 * CSANMAX) : thB * CSANMAX;
                    if (pT < n) outp[pT] = oT;
                    if (pB < n) outp[pB] = oB;
                }
            }
        }
        __syncwarp();
        t_c = t_n;
        idx_c = idx_n;
        s8_c = s8_n;
    }
}

extern "C" void kernel_launch(void* const* d_in, const int* in_sizes, int n_in,
                              void* d_out, int out_size)
{
    const int*   time_idx = (const int*)  d_in[0];
    const float* rho      = (const float*)d_in[1];
    const float* emb      = (const float*)d_in[2];
    const float* W0       = (const float*)d_in[3];
    const float* b0       = (const float*)d_in[4];
    const float* W1       = (const float*)d_in[5];
    const float* b1       = (const float*)d_in[6];
    const float* Wout     = (const float*)d_in[7];
    const float* bout     = (const float*)d_in[8];
    float* out = (float*)d_out;

    int n = in_sizes[0];
    int ntiles = (n + M_TILE - 1) / M_TILE;

    cudaFuncSetAttribute(slfm_hmma_kernel,
                         cudaFuncAttributeMaxDynamicSharedMemorySize, SM_TOTAL);
    int grid = ntiles < GRID_CTAS ? ntiles : GRID_CTAS;
    slfm_hmma_kernel<<<grid, TPB, SM_TOTAL>>>(time_idx, rho, emb, W0, b0, W1, b1,
                                              Wout, bout, out, n, ntiles);
}

// round 13
// speedup vs baseline: 9.7622x; 1.0529x over previous
#include <cuda_runtime.h>
#include <cuda_fp16.h>
#include <cstdint>
#include <math.h>

#define N_TIME   512
#define LATENT   32
#define HIDDEN   64
#define N_MODES  8
#define X_A0     0.3f
#define CSANMAX  28700.0f
#define BASE_LOGIT (-0.8472978603872034f)
#define PI_F 3.14159265358979323846f

#define TPB       128
#define M_TILE    128
#define GRID_CTAS 592

#define EMB_STRIDE_B  64   // bytes per emb row (32 fp16); 16B-aligned for ldmatrix
#define TRIG_STRIDE_B 48   // bytes per trig row; 16B-aligned, conflict-free

// ---- smem layout (bytes) ----
#define SM_EMB  0                          // 511 * 64 -> pad 32768
#define SM_TRIG 32768                      // 128 * 48 = 6144
#define SM_F0H  (SM_TRIG + 6144)           // 38912, 3ks*4ntp*32*16 = 6144
#define SM_F1H  (SM_F0H + 6144)            // 45056, 4ks -> 8192
#define SM_B0   (SM_F1H + 8192)            // 53248
#define SM_B1   (SM_B0 + 256)
#define SM_WO   (SM_B1 + 256)
#define SM_W48  (SM_WO + 256)              // W0 row 48 (fp32)
#define SM_BO   (SM_W48 + 256)
#define SM_TOTAL (SM_BO + 16)              // 54288 (~53 KB) -> 4 CTAs/SM

typedef uint32_t u32;

#define HALF2_HALF 0x38003800u   // fp16x2 {0.5, 0.5}

__device__ __forceinline__ u32 smem_u32(const void* p) {
    u32 a;
    asm("{ .reg .u64 t; cvta.to.shared.u64 t, %1; cvt.u32.u64 %0, t; }"
        : "=r"(a) : "l"(p));
    return a;
}

// pack two fp32 -> fp16x2, first arg in LOW half
__device__ __forceinline__ u32 pk16(float lo, float hi) {
    u32 r;
    asm("cvt.rn.f16x2.f32 %0, %1, %2;" : "=r"(r) : "f"(hi), "f"(lo));
    return r;
}

__device__ __forceinline__ float tanh_ap(float x) {
    float y; asm("tanh.approx.f32 %0, %1;" : "=f"(y) : "f"(x)); return y;
}

// packed silu on fp16x2: h = x * (0.5*tanh(0.5x) + 0.5). ONE MUFU per 2 elems.
__device__ __forceinline__ u32 silu_pk(u32 hx) {
    u32 t, th, s, r;
    asm("mul.f16x2 %0, %1, %2;" : "=r"(t)  : "r"(hx), "r"(HALF2_HALF));
    asm("tanh.approx.f16x2 %0, %1;" : "=r"(th) : "r"(t));
    asm("fma.rn.f16x2 %0, %1, %2, %3;" : "=r"(s) : "r"(th), "r"(HALF2_HALF), "r"(HALF2_HALF));
    asm("mul.f16x2 %0, %1, %2;" : "=r"(r) : "r"(hx), "r"(s));
    return r;
}

__device__ __forceinline__ void mma_fp16(float* d, u32 a0, u32 a1, u32 a2, u32 a3,
                                         u32 b0, u32 b1) {
    asm volatile("mma.sync.aligned.m16n8k16.row.col.f32.f16.f16.f32 "
                 "{%0,%1,%2,%3}, {%4,%5,%6,%7}, {%8,%9}, {%0,%1,%2,%3};"
                 : "+f"(d[0]), "+f"(d[1]), "+f"(d[2]), "+f"(d[3])
                 : "r"(a0), "r"(a1), "r"(a2), "r"(a3), "r"(b0), "r"(b1));
}

__device__ __forceinline__ void ldsm_x4(u32& r0, u32& r1, u32& r2, u32& r3, u32 addr) {
    asm volatile("ldmatrix.sync.aligned.m8n8.x4.shared.b16 {%0,%1,%2,%3}, [%4];"
                 : "=r"(r0), "=r"(r1), "=r"(r2), "=r"(r3) : "r"(addr));
}

// build trig features k=32..47 into trig smem row (tid), return sin(8*pi*rho)
// order: [rho, cos1..cos8, sin1..sin7]
__device__ __forceinline__ float build_trig(char* smem, int tid, float r) {
    float xv[16];
    xv[0] = r;
    float s1, c1;
    sincosf(PI_F * r, &s1, &c1);
    float ck = c1, sk = s1;
    xv[1] = ck; xv[9] = sk;
    float s8 = s1;
    #pragma unroll
    for (int k = 2; k <= N_MODES; k++) {
        float cn = fmaf(ck, c1, -sk * s1);
        float sn = fmaf(sk, c1,  ck * s1);
        ck = cn; sk = sn;
        xv[k] = ck;
        if (k < 8) xv[8 + k] = sk;
        else       s8 = sk;
    }
    uint4 v0 = make_uint4(pk16(xv[0], xv[1]), pk16(xv[2], xv[3]),
                          pk16(xv[4], xv[5]), pk16(xv[6], xv[7]));
    uint4 v1 = make_uint4(pk16(xv[8], xv[9]), pk16(xv[10], xv[11]),
                          pk16(xv[12], xv[13]), pk16(xv[14], xv[15]));
    char* rowp = smem + SM_TRIG + tid * TRIG_STRIDE_B;
    *(uint4*)(rowp)      = v0;
    *(uint4*)(rowp + 16) = v1;
    return s8;
}

__global__ __launch_bounds__(TPB, 4)
void slfm_hmma_kernel(const int* __restrict__ time_idx,
                      const float* __restrict__ rho,
                      const float* __restrict__ emb,
                      const float* __restrict__ W0,
                      const float* __restrict__ b0g,
                      const float* __restrict__ W1,
                      const float* __restrict__ b1g,
                      const float* __restrict__ Woutg,
                      const float* __restrict__ boutg,
                      float* __restrict__ outp,
                      int n, int ntiles)
{
    extern __shared__ char smem[];
    const u32 sb = smem_u32(smem);
    const int tid  = threadIdx.x;
    const int lane = tid & 31;
    const int warp = tid >> 5;
    const int g    = lane >> 2;
    const int t4   = lane & 3;
    const int rowA = warp * 32;

    // ---- stage emb table as fp16: row stride 64B, chunk q stored at q^(row&3) ----
    for (int i = tid; i < (N_TIME - 1) * 4; i += TPB) {
        int row = i >> 2, q = i & 3;
        const float4* e = (const float4*)(emb + row * LATENT) + q * 2;
        float4 e0 = e[0], e1 = e[1];
        uint4 v = make_uint4(pk16(e0.x, e0.y), pk16(e0.z, e0.w),
                             pk16(e1.x, e1.y), pk16(e1.z, e1.w));
        int qs = q ^ (row & 3);   // bank swizzle
        *(uint4*)(smem + SM_EMB + row * EMB_STRIDE_B + qs * 16) = v;
    }

    // ---- stage fp16 weight fragments (hi only) ----
    for (int i = tid; i < 512; i += TPB) {
        int ks = i >> 7, ntp = (i >> 5) & 3, ln = i & 31;
        int gg = ln >> 2, tt = ln & 3;
        int k0 = ks * 16 + tt * 2;

        {   // layer 1, all ks
            u32 hh[4];
            #pragma unroll
            for (int sub = 0; sub < 2; sub++) {
                int nn = (ntp * 2 + sub) * 8 + gg;
                hh[sub*2+0] = pk16(W1[(k0    ) * HIDDEN + nn],
                                   W1[(k0 + 1) * HIDDEN + nn]);
                hh[sub*2+1] = pk16(W1[(k0 + 8) * HIDDEN + nn],
                                   W1[(k0 + 9) * HIDDEN + nn]);
            }
            int off = ((ks * 4 + ntp) * 32 + ln) * 16;
            *(uint4*)(smem + SM_F1H + off) = make_uint4(hh[0], hh[1], hh[2], hh[3]);
        }
        if (ks < 3) {   // layer 0, k = 0..47
            u32 hh[4];
            #pragma unroll
            for (int sub = 0; sub < 2; sub++) {
                int nn = (ntp * 2 + sub) * 8 + gg;
                hh[sub*2+0] = pk16(W0[(k0    ) * HIDDEN + nn],
                                   W0[(k0 + 1) * HIDDEN + nn]);
                hh[sub*2+1] = pk16(W0[(k0 + 8) * HIDDEN + nn],
                                   W0[(k0 + 9) * HIDDEN + nn]);
            }
            int off = ((ks * 4 + ntp) * 32 + ln) * 16;
            *(uint4*)(smem + SM_F0H + off) = make_uint4(hh[0], hh[1], hh[2], hh[3]);
        }
    }
    if (tid < HIDDEN) {
        ((float*)(smem + SM_B0))[tid] = b0g[tid];
        ((float*)(smem + SM_B1))[tid] = b1g[tid];
        ((float*)(smem + SM_WO))[tid] = Woutg[tid];
        ((float*)(smem + SM_W48))[tid] = W0[48 * HIDDEN + tid];
    }
    if (tid == 0) *((float*)(smem + SM_BO)) = boutg[0] + BASE_LOGIT;

    // trig ldmatrix base (static per lane)
    const u32 trigBase = sb + SM_TRIG +
        (u32)((rowA + (lane & 15)) * TRIG_STRIDE_B + (lane >> 4) * 16);
    const int chunkSel = lane >> 4;   // 0 or 1

    // ---- prologue: first tile point data + trig ----
    int tile = blockIdx.x;
    int t_c = 0, idx_c = 0;
    float s8_c = 0.0f;
    if (tile < ntiles) {
        int p = tile * M_TILE + tid;
        int ps = p < n ? p : n - 1;
        t_c = time_idx[ps];
        float r0 = rho[ps];
        idx_c = t_c - 1;
        idx_c = idx_c < 0 ? 0 : (idx_c > N_TIME - 2 ? N_TIME - 2 : idx_c);
        s8_c = build_trig(smem, tid, r0);
    }
    __syncthreads();   // staging + trig visible

    // ---- loop-invariant Wout B-fragments (fp16): b0={Wout[k0],Wout[k0+1]},
    // b1={Wout[k0+8],Wout[k0+9]}, k0 = ks*16 + t4*2. Independent of g ->
    // every MMA N-column carries the same dot.
    u32 wb[4][2];
    {
        const float* wo = (const float*)(smem + SM_WO);
        #pragma unroll
        for (int ks = 0; ks < 4; ks++) {
            int k0 = ks * 16 + t4 * 2;
            wb[ks][0] = pk16(wo[k0],     wo[k0 + 1]);
            wb[ks][1] = pk16(wo[k0 + 8], wo[k0 + 9]);
        }
    }
    const float outb = *((const float*)(smem + SM_BO));  // bout + BASE_LOGIT

    for (; tile < ntiles; tile += GRID_CTAS) {
        // ---------- next-tile LDGs (tiny) ----------
        int ntile2 = tile + GRID_CTAS;
        int   t_n = 0, idx_n = 0;
        float r_n = 0.0f;
        if (ntile2 < ntiles) {
            int p = ntile2 * M_TILE + tid;
            int ps = p < n ? p : n - 1;
            t_n = time_idx[ps];
            r_n = rho[ps];
            idx_n = t_n - 1;
            idx_n = idx_n < 0 ? 0 : (idx_n > N_TIME - 2 ? N_TIME - 2 : idx_n);
        }

        // ---------- layer 0: A from emb table (ks 0,1) + trig (ks 2) ----------
        float d0[2][8][4];
        #pragma unroll
        for (int nt = 0; nt < 8; nt++) {
            int n0 = nt * 8 + t4 * 2;
            float2 bb = *(const float2*)(smem + SM_B0 + n0 * 4);
            #pragma unroll
            for (int mt = 0; mt < 2; mt++) {
                d0[mt][nt][0] = bb.x; d0[mt][nt][1] = bb.y;
                d0[mt][nt][2] = bb.x; d0[mt][nt][3] = bb.y;
            }
        }

        u32 ah[2][3][4];
        #pragma unroll
        for (int mt = 0; mt < 2; mt++) {
            int idxr = __shfl_sync(0xffffffffu, idx_c, (lane & 15) | (mt << 4));
            u32 rbase = sb + SM_EMB + (u32)idxr * EMB_STRIDE_B;
            int sw = idxr & 3;
            u32 a0 = rbase + (u32)((chunkSel ^ sw) * 16);           // chunks 0,1
            u32 a1 = rbase + (u32)(((chunkSel + 2) ^ sw) * 16);     // chunks 2,3
            ldsm_x4(ah[mt][0][0], ah[mt][0][1], ah[mt][0][2], ah[mt][0][3], a0);
            ldsm_x4(ah[mt][1][0], ah[mt][1][1], ah[mt][1][2], ah[mt][1][3], a1);
            u32 tb = trigBase + (u32)(mt * 16 * TRIG_STRIDE_B);
            ldsm_x4(ah[mt][2][0], ah[mt][2][1], ah[mt][2][2], ah[mt][2][3], tb);
        }

        #pragma unroll
        for (int ks = 0; ks < 3; ks++) {
            #pragma unroll
            for (int ntp = 0; ntp < 4; ntp++) {
                int off = ((ks * 4 + ntp) * 32 + lane) * 16;
                uint4 bh = *(const uint4*)(smem + SM_F0H + off);
                #pragma unroll
                for (int mt = 0; mt < 2; mt++) {
                    u32* a = ah[mt][ks];
                    mma_fp16(d0[mt][2*ntp],   a[0], a[1], a[2], a[3], bh.x, bh.y);
                    mma_fp16(d0[mt][2*ntp+1], a[0], a[1], a[2], a[3], bh.z, bh.w);
                }
            }
        }
        __syncwarp();   // warp's trig reads complete -> trig rows dead

        // ---------- rebuild trig for next tile ----------
        float s8_n = 0.0f;
        if (ntile2 < ntiles) s8_n = build_trig(smem, tid, r_n);

        // ---------- k=48 rank-1 fix: d0 += sin(8*pi*rho_row) * W0[48][col] ----------
        #pragma unroll
        for (int mt = 0; mt < 2; mt++) {
            float s8T = __shfl_sync(0xffffffffu, s8_c, mt * 16 + g);
            float s8B = __shfl_sync(0xffffffffu, s8_c, mt * 16 + g + 8);
            #pragma unroll
            for (int nt = 0; nt < 8; nt++) {
                int n0 = nt * 8 + t4 * 2;
                float2 w48 = *(const float2*)(smem + SM_W48 + n0 * 4);
                d0[mt][nt][0] = fmaf(s8T, w48.x, d0[mt][nt][0]);
                d0[mt][nt][1] = fmaf(s8T, w48.y, d0[mt][nt][1]);
                d0[mt][nt][2] = fmaf(s8B, w48.x, d0[mt][nt][2]);
                d0[mt][nt][3] = fmaf(s8B, w48.y, d0[mt][nt][3]);
            }
        }

        // ---------- epilogue 0: pack -> PACKED silu (f16x2) -> layer-1 A frags ----------
        u32 ah1[2][4][4];
        #pragma unroll
        for (int mt = 0; mt < 2; mt++) {
            #pragma unroll
            for (int ks = 0; ks < 4; ks++) {
                ah1[mt][ks][0] = silu_pk(pk16(d0[mt][2*ks][0],   d0[mt][2*ks][1]));
                ah1[mt][ks][1] = silu_pk(pk16(d0[mt][2*ks][2],   d0[mt][2*ks][3]));
                ah1[mt][ks][2] = silu_pk(pk16(d0[mt][2*ks+1][0], d0[mt][2*ks+1][1]));
                ah1[mt][ks][3] = silu_pk(pk16(d0[mt][2*ks+1][2], d0[mt][2*ks+1][3]));
            }
        }

        // ---------- layer 1 (d1 init with b1) ----------
        float d1[2][8][4];
        #pragma unroll
        for (int nt = 0; nt < 8; nt++) {
            int n0 = nt * 8 + t4 * 2;
            float2 bb = *(const float2*)(smem + SM_B1 + n0 * 4);
            #pragma unroll
            for (int mt = 0; mt < 2; mt++) {
                d1[mt][nt][0] = bb.x; d1[mt][nt][1] = bb.y;
                d1[mt][nt][2] = bb.x; d1[mt][nt][3] = bb.y;
            }
        }

        #pragma unroll
        for (int ks = 0; ks < 4; ks++) {
            #pragma unroll
            for (int ntp = 0; ntp < 4; ntp++) {
                int off = ((ks * 4 + ntp) * 32 + lane) * 16;
                uint4 bh = *(const uint4*)(smem + SM_F1H + off);
                #pragma unroll
                for (int mt = 0; mt < 2; mt++) {
                    u32* a = ah1[mt][ks];
                    mma_fp16(d1[mt][2*ntp],   a[0], a[1], a[2], a[3], bh.x, bh.y);
                    mma_fp16(d1[mt][2*ntp+1], a[0], a[1], a[2], a[3], bh.z, bh.w);
                }
            }
        }

        // ---------- final: PACKED silu -> A frags -> Wout dot ON TENSOR PIPE ----------
        // D = silu(H1) @ Wout_repl: every N column holds the same dot; no
        // shuffle reduce, no scalar dot. dd init = bout + BASE_LOGIT.
        #pragma unroll
        for (int mt = 0; mt < 2; mt++) {
            float dd[4] = {outb, outb, outb, outb};
            #pragma unroll
            for (int ks = 0; ks < 4; ks++) {
                u32 a0 = silu_pk(pk16(d1[mt][2*ks][0],   d1[mt][2*ks][1]));
                u32 a1 = silu_pk(pk16(d1[mt][2*ks][2],   d1[mt][2*ks][3]));
                u32 a2 = silu_pk(pk16(d1[mt][2*ks+1][0], d1[mt][2*ks+1][1]));
                u32 a3 = silu_pk(pk16(d1[mt][2*ks+1][2], d1[mt][2*ks+1][3]));
                mma_fp16(dd, a0, a1, a2, a3, wb[ks][0], wb[ks][1]);
            }
            // dd[0] = raw(row g), dd[2] = raw(row g+8)  (duplicated over t4)
            int rlT = mt * 16 + g;
            int rlB = rlT + 8;
            int tT = __shfl_sync(0xffffffffu, t_c, rlT);
            int tB = __shfl_sync(0xffffffffu, t_c, rlB);
            if (t4 == 0) {
                int pT = tile * M_TILE + rowA + rlT;
                int pB = tile * M_TILE + rowA + rlB;
                float thT = __fdividef(1.0f, 1.0f + __expf(-dd[0]));
                float thB = __fdividef(1.0f, 1.0f + __expf(-dd[2]));
                float oT = (tT == 0) ? (X_A0 * CSANMAX) : thT * CSANMAX;
                float oB = (tB == 0) ? (X_A0 * CSANMAX) : thB * CSANMAX;
                if (pT < n) outp[pT] = oT;
                if (pB < n) outp[pB] = oB;
            }
        }
        __syncwarp();
        t_c = t_n;
        idx_c = idx_n;
        s8_c = s8_n;
    }
}

extern "C" void kernel_launch(void* const* d_in, const int* in_sizes, int n_in,
                              void* d_out, int out_size)
{
    const int*   time_idx = (const int*)  d_in[0];
    const float* rho      = (const float*)d_in[1];
    const float* emb      = (const float*)d_in[2];
    const float* W0       = (const float*)d_in[3];
    const float* b0       = (const float*)d_in[4];
    const float* W1       = (const float*)d_in[5];
    const float* b1       = (const float*)d_in[6];
    const float* Wout     = (const float*)d_in[7];
    const float* bout     = (const float*)d_in[8];
    float* out = (float*)d_out;

    int n = in_sizes[0];
    int ntiles = (n + M_TILE - 1) / M_TILE;

    cudaFuncSetAttribute(slfm_hmma_kernel,
                         cudaFuncAttributeMaxDynamicSharedMemorySize, SM_TOTAL);
    int grid = ntiles < GRID_CTAS ? ntiles : GRID_CTAS;
    slfm_hmma_kernel<<<grid, TPB, SM_TOTAL>>>(time_idx, rho, emb, W0, b0, W1, b1,
                                              Wout, bout, out, n, ntiles);
}